// round 5
// baseline (speedup 1.0000x reference)
#include <cuda_runtime.h>
#include <math.h>

#define S_LEN   2048
#define D_MODEL 1024
#define N_HEADS 16
#define HEAD_DIM 64
#define BATCH   2
#define M_ROWS  (BATCH * S_LEN)   // 4096

// ---------------- device scratch (no allocations allowed) ----------------
__device__ float g_q[M_ROWS * D_MODEL];
__device__ float g_k[M_ROWS * D_MODEL];
__device__ float g_v[M_ROWS * D_MODEL];
__device__ float g_ctx[M_ROWS * D_MODEL];
__device__ float g_bias[N_HEADS * S_LEN];

// ---------------- packed f32x2 helpers ----------------
__device__ __forceinline__ unsigned long long pack2(float lo, float hi) {
    unsigned long long r;
    asm("mov.b64 %0, {%1, %2};" : "=l"(r) : "f"(lo), "f"(hi));
    return r;
}
__device__ __forceinline__ void unpack2(unsigned long long v, float& lo, float& hi) {
    asm("mov.b64 {%0, %1}, %2;" : "=f"(lo), "=f"(hi) : "l"(v));
}
#define FMA2(d, a, b) \
    asm("fma.rn.f32x2 %0, %1, %2, %3;" : "=l"(d) : "l"(a), "l"(b), "l"(d))

// ---------------- GEMM: C[M,N] = A[M,K] @ B[K,N], all row-major fp32 ----------------
#define BM 128
#define BN 128
#define BKT 16

__global__ __launch_bounds__(256, 2) void sgemm_kernel(
    const float* __restrict__ A, const float* __restrict__ B,
    float* __restrict__ C, int M, int N, int K)
{
    __shared__ float As[BKT][BM + 4];   // transposed A tile (pad 4)
    __shared__ float Bs[BKT][BN];

    const int tid = threadIdx.x;
    const int tx = tid & 15, ty = tid >> 4;
    const int m0 = ty * 8, n0 = tx * 8;
    const int gM = blockIdx.y * BM, gN = blockIdx.x * BN;

    unsigned long long acc[4][8];
#pragma unroll
    for (int i = 0; i < 4; i++)
#pragma unroll
        for (int j = 0; j < 8; j++) acc[i][j] = 0ull;

    for (int k0 = 0; k0 < K; k0 += BKT) {
#pragma unroll
        for (int it = 0; it < 2; it++) {
            int f = tid + 256 * it;
            int arow = f >> 2, akc = (f & 3) << 2;
            float4 va = *(const float4*)(A + (size_t)(gM + arow) * K + k0 + akc);
            As[akc + 0][arow] = va.x; As[akc + 1][arow] = va.y;
            As[akc + 2][arow] = va.z; As[akc + 3][arow] = va.w;
            int brow = f >> 5, bc = (f & 31) << 2;
            *(float4*)&Bs[brow][bc] =
                *(const float4*)(B + (size_t)(k0 + brow) * N + gN + bc);
        }
        __syncthreads();
#pragma unroll
        for (int kk = 0; kk < BKT; kk++) {
            float4 a0 = *(float4*)&As[kk][m0];
            float4 a1 = *(float4*)&As[kk][m0 + 4];
            float4 b0 = *(float4*)&Bs[kk][n0];
            float4 b1 = *(float4*)&Bs[kk][n0 + 4];
            unsigned long long a2[4];
            a2[0] = pack2(a0.x, a0.y); a2[1] = pack2(a0.z, a0.w);
            a2[2] = pack2(a1.x, a1.y); a2[3] = pack2(a1.z, a1.w);
            float bv[8] = {b0.x, b0.y, b0.z, b0.w, b1.x, b1.y, b1.z, b1.w};
#pragma unroll
            for (int j = 0; j < 8; j++) {
                unsigned long long bb = pack2(bv[j], bv[j]);
#pragma unroll
                for (int i = 0; i < 4; i++) FMA2(acc[i][j], a2[i], bb);
            }
        }
        __syncthreads();
    }
#pragma unroll
    for (int i = 0; i < 4; i++) {
#pragma unroll
        for (int j = 0; j < 8; j++) {
            float lo, hi;
            unpack2(acc[i][j], lo, hi);
            C[(size_t)(gM + m0 + 2 * i)     * N + gN + n0 + j] = lo;
            C[(size_t)(gM + m0 + 2 * i + 1) * N + gN + n0 + j] = hi;
        }
    }
}

// ---------------- RoPE in-place on q and k ----------------
// q'[i]    = q[i]*cos(a_i)    - q[i+32]*sin(a_i)
// q'[i+32] = q[i+32]*cos(a_i) + q[i]*sin(a_i),  a_i = s * base^(-2i/64)
__global__ void rope_kernel(float* __restrict__ q, float* __restrict__ k)
{
    const int m = blockIdx.x;          // 0..4095
    const int p = threadIdx.x;         // 0..511
    const int s = m & (S_LEN - 1);
    const int h = p >> 5, i = p & 31;

    // log2(10000) = 13.2877123795494...
    float inv = exp2f(-((float)(2 * i) * (1.0f / 64.0f)) * 13.287712379549449f);
    float ang = (float)s * inv;
    float sn, cs;
    __sincosf(ang, &sn, &cs);
    // use accurate sin/cos for large-argument safety
    cs = cosf(ang); sn = sinf(ang);

    size_t i0 = (size_t)m * D_MODEL + h * HEAD_DIM + i;
    float a = q[i0], b = q[i0 + 32];
    q[i0]      = a * cs - b * sn;
    q[i0 + 32] = b * cs + a * sn;
    a = k[i0]; b = k[i0 + 32];
    k[i0]      = a * cs - b * sn;
    k[i0 + 32] = b * cs + a * sn;
}

// ---------------- relative-position bias table: bias[h][delta], delta = q-k >= 0 ----------------
__global__ void bias_kernel(const float* __restrict__ rel_emb, float* __restrict__ bias)
{
    int idx = blockIdx.x * 256 + threadIdx.x;
    if (idx >= N_HEADS * S_LEN) return;
    int h = idx / S_LEN;
    int d = idx % S_LEN;
    int bucket;
    if (d < 16) {
        bucket = d;
    } else {
        float v = logf((float)d * (1.0f / 16.0f)) / logf(8.0f) * 16.0f;
        bucket = 16 + (int)v;
        if (bucket > 31) bucket = 31;
    }
    bias[idx] = rel_emb[bucket * N_HEADS + h];
}

// ---------------- flash attention: BQ = BKtile = 64, 128 threads ----------------
struct AttSmem {
    float Qt[64][68];    // [hd][row] transposed
    float Kt[64][68];    // [hd][key] transposed
    float Vs[64][68];    // [key][hd]
    float Ssc[64][68];   // scores -> probabilities
    float bias_s[128];
    float row_m[64];
    float row_l[64];
    float row_scale[64];
};

__global__ __launch_bounds__(128) void attn_kernel(
    const float* __restrict__ q, const float* __restrict__ k,
    const float* __restrict__ v, const float* __restrict__ bias,
    float* __restrict__ ctx)
{
    extern __shared__ char smem_raw[];
    AttSmem& sm = *reinterpret_cast<AttSmem*>(smem_raw);

    const int qb = (S_LEN / 64 - 1) - blockIdx.x;   // heavy q-blocks first
    const int bh = blockIdx.y;
    const int b  = bh >> 4;
    const int h  = bh & 15;
    const int tid = threadIdx.x;
    const int tx = tid & 15, ty = tid >> 4;
    const int r0 = ty * 8;       // 8 query rows per thread
    const int c0 = tx * 4;       // 4 keys (score phase) / 4 hd (PV phase)

    const float* qbase = q + ((size_t)b * S_LEN) * D_MODEL + h * HEAD_DIM;

    // load Q tile, transposed
#pragma unroll
    for (int it = 0; it < 8; it++) {
        int f = tid + 128 * it;
        int row = f >> 4, c4 = (f & 15) << 2;
        float4 vq = *(const float4*)(qbase + (size_t)(qb * 64 + row) * D_MODEL + c4);
        sm.Qt[c4 + 0][row] = vq.x; sm.Qt[c4 + 1][row] = vq.y;
        sm.Qt[c4 + 2][row] = vq.z; sm.Qt[c4 + 3][row] = vq.w;
    }
    if (tid < 64) { sm.row_m[tid] = -1e30f; sm.row_l[tid] = 0.0f; }

    float o_acc[8][4];
#pragma unroll
    for (int i = 0; i < 8; i++)
#pragma unroll
        for (int j = 0; j < 4; j++) o_acc[i][j] = 0.0f;
    __syncthreads();

    for (int kt = 0; kt <= qb; kt++) {
        const float* kbase = k + ((size_t)b * S_LEN + kt * 64) * D_MODEL + h * HEAD_DIM;
        const float* vbase = v + ((size_t)b * S_LEN + kt * 64) * D_MODEL + h * HEAD_DIM;
#pragma unroll
        for (int it = 0; it < 8; it++) {
            int f = tid + 128 * it;
            int row = f >> 4, c4 = (f & 15) << 2;
            float4 vk = *(const float4*)(kbase + (size_t)row * D_MODEL + c4);
            sm.Kt[c4 + 0][row] = vk.x; sm.Kt[c4 + 1][row] = vk.y;
            sm.Kt[c4 + 2][row] = vk.z; sm.Kt[c4 + 3][row] = vk.w;
            float4 vv = *(const float4*)(vbase + (size_t)row * D_MODEL + c4);
            *(float4*)&sm.Vs[row][c4] = vv;
        }
        {
            int dlt = (qb - kt) * 64 - 63 + tid;
            int dcl = dlt < 0 ? 0 : (dlt > S_LEN - 1 ? S_LEN - 1 : dlt);
            sm.bias_s[tid] = bias[h * S_LEN + dcl];
        }
        __syncthreads();

        // ---- scores: S[r][c] = sum_hd Q[r][hd]*K[c][hd] ----
        float sacc[8][4];
#pragma unroll
        for (int i = 0; i < 8; i++)
#pragma unroll
            for (int j = 0; j < 4; j++) sacc[i][j] = 0.0f;

#pragma unroll 8
        for (int hd = 0; hd < 64; hd++) {
            float4 qa = *(const float4*)&sm.Qt[hd][r0];
            float4 qc = *(const float4*)&sm.Qt[hd][r0 + 4];
            float4 kb = *(const float4*)&sm.Kt[hd][c0];
            float av[8] = {qa.x, qa.y, qa.z, qa.w, qc.x, qc.y, qc.z, qc.w};
            float bv[4] = {kb.x, kb.y, kb.z, kb.w};
#pragma unroll
            for (int i = 0; i < 8; i++)
#pragma unroll
                for (int j = 0; j < 4; j++) sacc[i][j] += av[i] * bv[j];
        }

        const bool diag = (kt == qb);
#pragma unroll
        for (int i = 0; i < 8; i++) {
            int rl = r0 + i;
            float4 sv4;
            float* svp = (float*)&sv4;
#pragma unroll
            for (int j = 0; j < 4; j++) {
                int kl = c0 + j;
                float sv = sacc[i][j] * 0.125f + sm.bias_s[rl - kl + 63];
                if (diag && kl > rl) sv = -1e9f;
                svp[j] = sv;
            }
            *(float4*)&sm.Ssc[rl][c0] = sv4;
        }
        __syncthreads();

        // ---- online softmax (2 threads per row) ----
        {
            int r = tid >> 1, half = tid & 1;
            int cb = half * 32;
            float mloc = -1e30f;
#pragma unroll
            for (int jj = 0; jj < 32; jj++) mloc = fmaxf(mloc, sm.Ssc[r][cb + jj]);
            mloc = fmaxf(mloc, __shfl_xor_sync(0xffffffffu, mloc, 1));
            float m_old = sm.row_m[r];
            float m_new = fmaxf(m_old, mloc);
            float corr = __expf(m_old - m_new);
            float lsum = 0.0f;
#pragma unroll
            for (int jj = 0; jj < 32; jj++) {
                float p = __expf(sm.Ssc[r][cb + jj] - m_new);
                sm.Ssc[r][cb + jj] = p;
                lsum += p;
            }
            lsum += __shfl_xor_sync(0xffffffffu, lsum, 1);
            __syncwarp();
            if (half == 0) {
                sm.row_l[r] = sm.row_l[r] * corr + lsum;
                sm.row_m[r] = m_new;
                sm.row_scale[r] = corr;
            }
        }
        __syncthreads();

        // ---- O = O*corr + P @ V ----
#pragma unroll
        for (int i = 0; i < 8; i++) {
            float cr = sm.row_scale[r0 + i];
#pragma unroll
            for (int j = 0; j < 4; j++) o_acc[i][j] *= cr;
        }
#pragma unroll 8
        for (int kk2 = 0; kk2 < 64; kk2++) {
            float4 vv = *(const float4*)&sm.Vs[kk2][c0];
            float vb[4] = {vv.x, vv.y, vv.z, vv.w};
#pragma unroll
            for (int i = 0; i < 8; i++) {
                float p = sm.Ssc[r0 + i][kk2];
#pragma unroll
                for (int j = 0; j < 4; j++) o_acc[i][j] += p * vb[j];
            }
        }
        __syncthreads();
    }

    // ---- epilogue: divide by l, write ctx in [b,s,h,hd] layout ----
#pragma unroll
    for (int i = 0; i < 8; i++) {
        float inv = 1.0f / sm.row_l[r0 + i];
        float4 o;
        o.x = o_acc[i][0] * inv; o.y = o_acc[i][1] * inv;
        o.z = o_acc[i][2] * inv; o.w = o_acc[i][3] * inv;
        *(float4*)(ctx + (size_t)(b * S_LEN + qb * 64 + r0 + i) * D_MODEL
                       + h * HEAD_DIM + c0) = o;
    }
}

// ---------------- launcher ----------------
extern "C" void kernel_launch(void* const* d_in, const int* in_sizes, int n_in,
                              void* d_out, int out_size)
{
    const float* x   = (const float*)d_in[0];
    const float* Wq  = (const float*)d_in[1];
    const float* Wk  = (const float*)d_in[2];
    const float* Wv  = (const float*)d_in[3];
    const float* Wo  = (const float*)d_in[4];
    const float* rel = (const float*)d_in[5];

    float *qp, *kp, *vp, *cp, *bp;
    cudaGetSymbolAddress((void**)&qp, g_q);
    cudaGetSymbolAddress((void**)&kp, g_k);
    cudaGetSymbolAddress((void**)&vp, g_v);
    cudaGetSymbolAddress((void**)&cp, g_ctx);
    cudaGetSymbolAddress((void**)&bp, g_bias);

    dim3 gg(D_MODEL / BN, M_ROWS / BM);   // (8, 32)

    sgemm_kernel<<<gg, 256>>>(x, Wq, qp, M_ROWS, D_MODEL, D_MODEL);
    sgemm_kernel<<<gg, 256>>>(x, Wk, kp, M_ROWS, D_MODEL, D_MODEL);
    sgemm_kernel<<<gg, 256>>>(x, Wv, vp, M_ROWS, D_MODEL, D_MODEL);

    rope_kernel<<<M_ROWS, 512>>>(qp, kp);
    bias_kernel<<<(N_HEADS * S_LEN + 255) / 256, 256>>>(rel, bp);

    cudaFuncSetAttribute(attn_kernel, cudaFuncAttributeMaxDynamicSharedMemorySize,
                         (int)sizeof(AttSmem));
    attn_kernel<<<dim3(S_LEN / 64, BATCH * N_HEADS), 128, sizeof(AttSmem)>>>(
        qp, kp, vp, bp, cp);

    sgemm_kernel<<<gg, 256>>>(cp, Wo, (float*)d_out, M_ROWS, D_MODEL, D_MODEL);
}

// round 8
// speedup vs baseline: 1.5335x; 1.5335x over previous
#include <cuda_runtime.h>
#include <cuda_bf16.h>
#include <math.h>
#include <stdint.h>

#define S_LEN   2048
#define D_MODEL 1024
#define N_HEADS 16
#define HEAD_DIM 64
#define BATCH   2
#define M_ROWS  (BATCH * S_LEN)   // 4096

// ---------------- device scratch (no allocations allowed) ----------------
__device__ float g_q[M_ROWS * D_MODEL];
__device__ float g_k[M_ROWS * D_MODEL];
__device__ float g_v[M_ROWS * D_MODEL];
__device__ float g_ctx[M_ROWS * D_MODEL];
__device__ float g_bias[N_HEADS * S_LEN];
__device__ __nv_bfloat16 g_ahi[M_ROWS * D_MODEL];
__device__ __nv_bfloat16 g_alo[M_ROWS * D_MODEL];
__device__ __nv_bfloat16 g_whi[4][D_MODEL * D_MODEL];   // transposed [N][K]
__device__ __nv_bfloat16 g_wlo[4][D_MODEL * D_MODEL];

// ---------------- packed f32x2 helpers ----------------
__device__ __forceinline__ unsigned long long pack2(float lo, float hi) {
    unsigned long long r;
    asm("mov.b64 %0, {%1, %2};" : "=l"(r) : "f"(lo), "f"(hi));
    return r;
}
__device__ __forceinline__ void unpack2(unsigned long long v, float& lo, float& hi) {
    asm("mov.b64 {%0, %1}, %2;" : "=f"(lo), "=f"(hi) : "l"(v));
}
#define FMA2(d, a, b) \
    asm("fma.rn.f32x2 %0, %1, %2, %3;" : "=l"(d) : "l"(a), "l"(b), "l"(d))
#define MUL2(d, a, b) \
    asm("mul.rn.f32x2 %0, %1, %2;" : "=l"(d) : "l"(a), "l"(b))

// ---------------- bf16 mma.sync (family-agnostic, sm_80+ -> HMMA) ----------
#define MMA_BF16(d, a, b) \
    asm volatile( \
        "mma.sync.aligned.m16n8k16.row.col.f32.bf16.bf16.f32 " \
        "{%0,%1,%2,%3}, {%4,%5,%6,%7}, {%8,%9}, {%0,%1,%2,%3};" \
        : "+f"((d)[0]), "+f"((d)[1]), "+f"((d)[2]), "+f"((d)[3]) \
        : "r"((a)[0]), "r"((a)[1]), "r"((a)[2]), "r"((a)[3]), \
          "r"((b)[0]), "r"((b)[1]))

// ---------------- hi/lo bf16 conversion kernels ----------------
__global__ void conv_act_kernel(const float* __restrict__ in,
                                __nv_bfloat16* __restrict__ hi,
                                __nv_bfloat16* __restrict__ lo)
{
    size_t base = ((size_t)blockIdx.x * 256 + threadIdx.x) * 4;
    float4 v = *(const float4*)(in + base);
    __nv_bfloat16 h0 = __float2bfloat16(v.x);
    __nv_bfloat16 h1 = __float2bfloat16(v.y);
    __nv_bfloat16 h2 = __float2bfloat16(v.z);
    __nv_bfloat16 h3 = __float2bfloat16(v.w);
    ushort4 hs = { __bfloat16_as_ushort(h0), __bfloat16_as_ushort(h1),
                   __bfloat16_as_ushort(h2), __bfloat16_as_ushort(h3) };
    __nv_bfloat16 l0 = __float2bfloat16(v.x - __bfloat162float(h0));
    __nv_bfloat16 l1 = __float2bfloat16(v.y - __bfloat162float(h1));
    __nv_bfloat16 l2 = __float2bfloat16(v.z - __bfloat162float(h2));
    __nv_bfloat16 l3 = __float2bfloat16(v.w - __bfloat162float(h3));
    ushort4 ls = { __bfloat16_as_ushort(l0), __bfloat16_as_ushort(l1),
                   __bfloat16_as_ushort(l2), __bfloat16_as_ushort(l3) };
    *(ushort4*)(hi + base) = hs;
    *(ushort4*)(lo + base) = ls;
}

// W [K,N] fp32 -> Wt [N,K] bf16 hi/lo
__global__ void conv_wt_kernel(const float* __restrict__ W,
                               __nv_bfloat16* __restrict__ hi,
                               __nv_bfloat16* __restrict__ lo)
{
    __shared__ float t[32][33];
    const int x0 = blockIdx.x * 32, y0 = blockIdx.y * 32;
    const int tx = threadIdx.x, ty = threadIdx.y;
#pragma unroll
    for (int j = 0; j < 4; j++) {
        int r = ty + j * 8;
        t[r][tx] = W[(size_t)(y0 + r) * D_MODEL + x0 + tx];
    }
    __syncthreads();
#pragma unroll
    for (int j = 0; j < 4; j++) {
        int r = ty + j * 8;                 // output row n = x0 + r
        float v = t[tx][r];                 // = W[y0+tx][x0+r]
        __nv_bfloat16 h = __float2bfloat16(v);
        size_t o = (size_t)(x0 + r) * D_MODEL + y0 + tx;
        hi[o] = h;
        lo[o] = __float2bfloat16(v - __bfloat162float(h));
    }
}

// ---------------- HMMA GEMM: C[4096,1024] = A @ W  (3-term bf16 split) -----
// A hi/lo [M,K] bf16 row-major; B hi/lo [N,K] bf16 (pre-transposed weights,
// which is exactly the col-major layout m16n8k16.row.col wants).
// Block 256 thr, tile 128x128, K-chunk 64. Warp grid 2(m) x 4(n), warp tile 64x32.
// SMEM tiles 128 rows x 64 bf16 (128 B/row), xor swizzle: 16B-chunk ^= row&7.

#define KC 64
#define TILE_BYTES (128 * KC * 2)          // 16384
#define SM_AHI 0
#define SM_ALO (TILE_BYTES)
#define SM_BHI (2 * TILE_BYTES)
#define SM_BLO (3 * TILE_BYTES)
#define GEMM_SMEM (4 * TILE_BYTES)         // 65536

__device__ __forceinline__ uint32_t lds_b32_sw(const char* base, int row, int kbyte) {
    int off = row * 128 + ((((kbyte >> 4) ^ (row & 7)) & 7) << 4) + (kbyte & 15);
    return *(const uint32_t*)(base + off);
}

__global__ __launch_bounds__(256) void hmma_gemm_kernel(
    const __nv_bfloat16* __restrict__ Ahi, const __nv_bfloat16* __restrict__ Alo,
    const __nv_bfloat16* __restrict__ Bhi, const __nv_bfloat16* __restrict__ Blo,
    float* __restrict__ C)
{
    extern __shared__ char smem[];
    const int tid = threadIdx.x;
    const int wid = tid >> 5, lane = tid & 31;
    const int g = lane >> 2, tg = lane & 3;
    const int mw = wid & 1, nw = wid >> 1;        // 2 x 4 warp grid
    const int mBase = mw * 64, nBase = nw * 32;
    const int gM = blockIdx.y * 128, gN = blockIdx.x * 128;

    float d[4][4][4];                             // [mt][nt][frag]
#pragma unroll
    for (int mt = 0; mt < 4; mt++)
#pragma unroll
        for (int nt = 0; nt < 4; nt++)
#pragma unroll
            for (int f = 0; f < 4; f++) d[mt][nt][f] = 0.0f;

    for (int k0 = 0; k0 < D_MODEL; k0 += KC) {
        // ---- stage 4 tiles: each 128 rows x 64 bf16, 16B chunks swizzled ----
#pragma unroll
        for (int t = 0; t < 4; t++) {
            const __nv_bfloat16* src =
                (t == 0) ? Ahi : (t == 1) ? Alo : (t == 2) ? Bhi : Blo;
            const int gBase = (t < 2) ? gM : gN;
            char* dst = smem + t * TILE_BYTES;
#pragma unroll
            for (int it = 0; it < 4; it++) {
                int slot = it * 256 + tid;        // 1024 slots
                int row = slot >> 3, ch = slot & 7;
                uint4 val = *(const uint4*)(src + (size_t)(gBase + row) * D_MODEL
                                            + k0 + ch * 8);
                *(uint4*)(dst + row * 128 + ((ch ^ (row & 7)) << 4)) = val;
            }
        }
        __syncthreads();

        const char* sAh = smem + SM_AHI;
        const char* sAl = smem + SM_ALO;
        const char* sBh = smem + SM_BHI;
        const char* sBl = smem + SM_BLO;

#pragma unroll
        for (int ks = 0; ks < 4; ks++) {
            const int kb0 = ks * 32 + tg * 4;     // k 0-7 of this k16
            const int kb1 = kb0 + 16;             // k 8-15
            uint32_t ah[4][4], al[4][4];
#pragma unroll
            for (int mt = 0; mt < 4; mt++) {
                int r0 = mBase + mt * 16 + g, r1 = r0 + 8;
                ah[mt][0] = lds_b32_sw(sAh, r0, kb0);
                ah[mt][1] = lds_b32_sw(sAh, r1, kb0);
                ah[mt][2] = lds_b32_sw(sAh, r0, kb1);
                ah[mt][3] = lds_b32_sw(sAh, r1, kb1);
                al[mt][0] = lds_b32_sw(sAl, r0, kb0);
                al[mt][1] = lds_b32_sw(sAl, r1, kb0);
                al[mt][2] = lds_b32_sw(sAl, r0, kb1);
                al[mt][3] = lds_b32_sw(sAl, r1, kb1);
            }
            uint32_t bh[4][2], bl[4][2];
#pragma unroll
            for (int nt = 0; nt < 4; nt++) {
                int n = nBase + nt * 8 + g;
                bh[nt][0] = lds_b32_sw(sBh, n, kb0);
                bh[nt][1] = lds_b32_sw(sBh, n, kb1);
                bl[nt][0] = lds_b32_sw(sBl, n, kb0);
                bl[nt][1] = lds_b32_sw(sBl, n, kb1);
            }
#pragma unroll
            for (int mt = 0; mt < 4; mt++)
#pragma unroll
                for (int nt = 0; nt < 4; nt++) {
                    MMA_BF16(d[mt][nt], ah[mt], bh[nt]);
                    MMA_BF16(d[mt][nt], ah[mt], bl[nt]);
                    MMA_BF16(d[mt][nt], al[mt], bh[nt]);
                }
        }
        __syncthreads();
    }

    // ---- store C ----
#pragma unroll
    for (int mt = 0; mt < 4; mt++) {
#pragma unroll
        for (int nt = 0; nt < 4; nt++) {
            int m = gM + mBase + mt * 16 + g;
            int n = gN + nBase + nt * 8 + tg * 2;
            float2 v0 = { d[mt][nt][0], d[mt][nt][1] };
            float2 v1 = { d[mt][nt][2], d[mt][nt][3] };
            *(float2*)(C + (size_t)m * D_MODEL + n) = v0;
            *(float2*)(C + (size_t)(m + 8) * D_MODEL + n) = v1;
        }
    }
}

// ---------------- RoPE in-place on q and k ----------------
__global__ void rope_kernel(float* __restrict__ q, float* __restrict__ k)
{
    const int m = blockIdx.x;
    const int p = threadIdx.x;
    const int s = m & (S_LEN - 1);
    const int h = p >> 5, i = p & 31;

    float inv = exp2f(-((float)(2 * i) * (1.0f / 64.0f)) * 13.287712379549449f);
    float ang = (float)s * inv;
    float cs = cosf(ang), sn = sinf(ang);

    size_t i0 = (size_t)m * D_MODEL + h * HEAD_DIM + i;
    float a = q[i0], b = q[i0 + 32];
    q[i0]      = a * cs - b * sn;
    q[i0 + 32] = b * cs + a * sn;
    a = k[i0]; b = k[i0 + 32];
    k[i0]      = a * cs - b * sn;
    k[i0 + 32] = b * cs + a * sn;
}

// ---------------- relative-position bias table ----------------
__global__ void bias_kernel(const float* __restrict__ rel_emb, float* __restrict__ bias)
{
    int idx = blockIdx.x * 256 + threadIdx.x;
    if (idx >= N_HEADS * S_LEN) return;
    int h = idx / S_LEN;
    int d = idx % S_LEN;
    int bucket;
    if (d < 16) {
        bucket = d;
    } else {
        float v = logf((float)d * (1.0f / 16.0f)) / logf(8.0f) * 16.0f;
        bucket = 16 + (int)v;
        if (bucket > 31) bucket = 31;
    }
    bias[idx] = rel_emb[bucket * N_HEADS + h];
}

// ---------------- flash attention: BQ = BK = 64, 128 threads, f32x2 inner ----
struct AttSmem {
    float Qt[64][68];
    float Kt[64][68];
    float Vs[64][68];
    float Ssc[64][68];
    float bias_s[128];
    float row_m[64];
    float row_l[64];
    float row_scale[64];
};

__global__ __launch_bounds__(128) void attn_kernel(
    const float* __restrict__ q, const float* __restrict__ k,
    const float* __restrict__ v, const float* __restrict__ bias,
    float* __restrict__ ctx)
{
    extern __shared__ char smem_raw[];
    AttSmem& sm = *reinterpret_cast<AttSmem*>(smem_raw);

    const int qb = (S_LEN / 64 - 1) - blockIdx.x;
    const int bh = blockIdx.y;
    const int b  = bh >> 4;
    const int h  = bh & 15;
    const int tid = threadIdx.x;
    const int tx = tid & 15, ty = tid >> 4;
    const int r0 = ty * 8;
    const int c0 = tx * 4;

    const float* qbase = q + ((size_t)b * S_LEN) * D_MODEL + h * HEAD_DIM;

#pragma unroll
    for (int it = 0; it < 8; it++) {
        int f = tid + 128 * it;
        int row = f >> 4, c4 = (f & 15) << 2;
        float4 vq = *(const float4*)(qbase + (size_t)(qb * 64 + row) * D_MODEL + c4);
        sm.Qt[c4 + 0][row] = vq.x; sm.Qt[c4 + 1][row] = vq.y;
        sm.Qt[c4 + 2][row] = vq.z; sm.Qt[c4 + 3][row] = vq.w;
    }
    if (tid < 64) { sm.row_m[tid] = -1e30f; sm.row_l[tid] = 0.0f; }

    unsigned long long o2[8][2];
#pragma unroll
    for (int i = 0; i < 8; i++) { o2[i][0] = 0ull; o2[i][1] = 0ull; }
    __syncthreads();

    for (int kt = 0; kt <= qb; kt++) {
        const float* kbase = k + ((size_t)b * S_LEN + kt * 64) * D_MODEL + h * HEAD_DIM;
        const float* vbase = v + ((size_t)b * S_LEN + kt * 64) * D_MODEL + h * HEAD_DIM;
#pragma unroll
        for (int it = 0; it < 8; it++) {
            int f = tid + 128 * it;
            int row = f >> 4, c4 = (f & 15) << 2;
            float4 vk = *(const float4*)(kbase + (size_t)row * D_MODEL + c4);
            sm.Kt[c4 + 0][row] = vk.x; sm.Kt[c4 + 1][row] = vk.y;
            sm.Kt[c4 + 2][row] = vk.z; sm.Kt[c4 + 3][row] = vk.w;
            float4 vv = *(const float4*)(vbase + (size_t)row * D_MODEL + c4);
            *(float4*)&sm.Vs[row][c4] = vv;
        }
        {
            int dlt = (qb - kt) * 64 - 63 + tid;
            int dcl = dlt < 0 ? 0 : (dlt > S_LEN - 1 ? S_LEN - 1 : dlt);
            sm.bias_s[tid] = bias[h * S_LEN + dcl];
        }
        __syncthreads();

        // ---- scores via f32x2: s2[p][j] = rows (2p,2p+1) x col j ----
        unsigned long long s2[4][4];
#pragma unroll
        for (int p = 0; p < 4; p++)
#pragma unroll
            for (int j = 0; j < 4; j++) s2[p][j] = 0ull;

#pragma unroll 8
        for (int hd = 0; hd < 64; hd++) {
            float4 qa = *(const float4*)&sm.Qt[hd][r0];
            float4 qc = *(const float4*)&sm.Qt[hd][r0 + 4];
            float4 kb = *(const float4*)&sm.Kt[hd][c0];
            unsigned long long a2[4];
            a2[0] = pack2(qa.x, qa.y); a2[1] = pack2(qa.z, qa.w);
            a2[2] = pack2(qc.x, qc.y); a2[3] = pack2(qc.z, qc.w);
            float bvv[4] = {kb.x, kb.y, kb.z, kb.w};
#pragma unroll
            for (int j = 0; j < 4; j++) {
                unsigned long long bb = pack2(bvv[j], bvv[j]);
#pragma unroll
                for (int p = 0; p < 4; p++) FMA2(s2[p][j], a2[p], bb);
            }
        }

        float sacc[8][4];
#pragma unroll
        for (int p = 0; p < 4; p++)
#pragma unroll
            for (int j = 0; j < 4; j++)
                unpack2(s2[p][j], sacc[2 * p][j], sacc[2 * p + 1][j]);

        const bool diag = (kt == qb);
#pragma unroll
        for (int i = 0; i < 8; i++) {
            int rl = r0 + i;
            float4 sv4;
            float* svp = (float*)&sv4;
#pragma unroll
            for (int j = 0; j < 4; j++) {
                int kl = c0 + j;
                float sv = sacc[i][j] * 0.125f + sm.bias_s[rl - kl + 63];
                if (diag && kl > rl) sv = -1e9f;
                svp[j] = sv;
            }
            *(float4*)&sm.Ssc[rl][c0] = sv4;
        }
        __syncthreads();

        // ---- online softmax (2 threads per row) ----
        {
            int r = tid >> 1, half = tid & 1;
            int cb = half * 32;
            float mloc = -1e30f;
#pragma unroll
            for (int jj = 0; jj < 32; jj++) mloc = fmaxf(mloc, sm.Ssc[r][cb + jj]);
            mloc = fmaxf(mloc, __shfl_xor_sync(0xffffffffu, mloc, 1));
            float m_old = sm.row_m[r];
            float m_new = fmaxf(m_old, mloc);
            float corr = __expf(m_old - m_new);
            float lsum = 0.0f;
#pragma unroll
            for (int jj = 0; jj < 32; jj++) {
                float p = __expf(sm.Ssc[r][cb + jj] - m_new);
                sm.Ssc[r][cb + jj] = p;
                lsum += p;
            }
            lsum += __shfl_xor_sync(0xffffffffu, lsum, 1);
            __syncwarp();
            if (half == 0) {
                sm.row_l[r] = sm.row_l[r] * corr + lsum;
                sm.row_m[r] = m_new;
                sm.row_scale[r] = corr;
            }
        }
        __syncthreads();

        // ---- O = O*corr + P @ V (f32x2) ----
#pragma unroll
        for (int i = 0; i < 8; i++) {
            float cr = sm.row_scale[r0 + i];
            unsigned long long cr2 = pack2(cr, cr);
            MUL2(o2[i][0], o2[i][0], cr2);
            MUL2(o2[i][1], o2[i][1], cr2);
        }
#pragma unroll 8
        for (int kk2 = 0; kk2 < 64; kk2++) {
            float4 vv = *(const float4*)&sm.Vs[kk2][c0];
            unsigned long long v01 = pack2(vv.x, vv.y);
            unsigned long long v23 = pack2(vv.z, vv.w);
#pragma unroll
            for (int i = 0; i < 8; i++) {
                float p = sm.Ssc[r0 + i][kk2];
                unsigned long long pp = pack2(p, p);
                FMA2(o2[i][0], pp, v01);
                FMA2(o2[i][1], pp, v23);
            }
        }
        __syncthreads();
    }

    // ---- epilogue ----
#pragma unroll
    for (int i = 0; i < 8; i++) {
        float inv = 1.0f / sm.row_l[r0 + i];
        float a, bq, c, dd;
        unpack2(o2[i][0], a, bq);
        unpack2(o2[i][1], c, dd);
        float4 o;
        o.x = a * inv; o.y = bq * inv; o.z = c * inv; o.w = dd * inv;
        *(float4*)(ctx + (size_t)(b * S_LEN + qb * 64 + r0 + i) * D_MODEL
                       + h * HEAD_DIM + c0) = o;
    }
}

// ---------------- launcher ----------------
extern "C" void kernel_launch(void* const* d_in, const int* in_sizes, int n_in,
                              void* d_out, int out_size)
{
    const float* x   = (const float*)d_in[0];
    const float* Wq  = (const float*)d_in[1];
    const float* Wk  = (const float*)d_in[2];
    const float* Wv  = (const float*)d_in[3];
    const float* Wo  = (const float*)d_in[4];
    const float* rel = (const float*)d_in[5];

    float *qp, *kp, *vp, *cp, *bp;
    __nv_bfloat16 *ahi, *alo, *whi, *wlo;
    cudaGetSymbolAddress((void**)&qp, g_q);
    cudaGetSymbolAddress((void**)&kp, g_k);
    cudaGetSymbolAddress((void**)&vp, g_v);
    cudaGetSymbolAddress((void**)&cp, g_ctx);
    cudaGetSymbolAddress((void**)&bp, g_bias);
    cudaGetSymbolAddress((void**)&ahi, g_ahi);
    cudaGetSymbolAddress((void**)&alo, g_alo);
    cudaGetSymbolAddress((void**)&whi, g_whi);
    cudaGetSymbolAddress((void**)&wlo, g_wlo);

    const size_t WSTRIDE = (size_t)D_MODEL * D_MODEL;
    const float* Ws[4] = {Wq, Wk, Wv, Wo};

    // conversions
    conv_act_kernel<<<M_ROWS * D_MODEL / (256 * 4), 256>>>(x, ahi, alo);
    for (int w = 0; w < 4; w++)
        conv_wt_kernel<<<dim3(32, 32), dim3(32, 8)>>>(Ws[w], whi + w * WSTRIDE,
                                                      wlo + w * WSTRIDE);
    bias_kernel<<<(N_HEADS * S_LEN + 255) / 256, 256>>>(rel, bp);

    // QKV projections on HMMA tensor cores
    cudaFuncSetAttribute(hmma_gemm_kernel, cudaFuncAttributeMaxDynamicSharedMemorySize,
                         GEMM_SMEM);
    dim3 gg(D_MODEL / 128, M_ROWS / 128);   // (8, 32)
    hmma_gemm_kernel<<<gg, 256, GEMM_SMEM>>>(ahi, alo, whi + 0 * WSTRIDE,
                                             wlo + 0 * WSTRIDE, qp);
    hmma_gemm_kernel<<<gg, 256, GEMM_SMEM>>>(ahi, alo, whi + 1 * WSTRIDE,
                                             wlo + 1 * WSTRIDE, kp);
    hmma_gemm_kernel<<<gg, 256, GEMM_SMEM>>>(ahi, alo, whi + 2 * WSTRIDE,
                                             wlo + 2 * WSTRIDE, vp);

    rope_kernel<<<M_ROWS, 512>>>(qp, kp);

    cudaFuncSetAttribute(attn_kernel, cudaFuncAttributeMaxDynamicSharedMemorySize,
                         (int)sizeof(AttSmem));
    attn_kernel<<<dim3(S_LEN / 64, BATCH * N_HEADS), 128, sizeof(AttSmem)>>>(
        qp, kp, vp, bp, cp);

    // output projection
    conv_act_kernel<<<M_ROWS * D_MODEL / (256 * 4), 256>>>(cp, ahi, alo);
    hmma_gemm_kernel<<<gg, 256, GEMM_SMEM>>>(ahi, alo, whi + 3 * WSTRIDE,
                                             wlo + 3 * WSTRIDE, (float*)d_out);
}

// round 9
// speedup vs baseline: 2.4474x; 1.5960x over previous
#include <cuda_runtime.h>
#include <cuda_bf16.h>
#include <math.h>
#include <stdint.h>

#define S_LEN   2048
#define D_MODEL 1024
#define N_HEADS 16
#define HEAD_DIM 64
#define BATCH   2
#define M_ROWS  (BATCH * S_LEN)   // 4096

// ---------------- device scratch (no allocations allowed) ----------------
__device__ float g_q[M_ROWS * D_MODEL];
__device__ float g_k[M_ROWS * D_MODEL];
__device__ float g_v[M_ROWS * D_MODEL];
__device__ float g_ctx[M_ROWS * D_MODEL];
__device__ float g_bias[N_HEADS * S_LEN];
__device__ __nv_bfloat16 g_ahi[M_ROWS * D_MODEL];
__device__ __nv_bfloat16 g_alo[M_ROWS * D_MODEL];
__device__ __nv_bfloat16 g_whi[4][D_MODEL * D_MODEL];   // transposed [N][K]
__device__ __nv_bfloat16 g_wlo[4][D_MODEL * D_MODEL];
// attention operands (bf16 hi/lo)
__device__ __nv_bfloat16 g_qhi[M_ROWS * D_MODEL];
__device__ __nv_bfloat16 g_qlo[M_ROWS * D_MODEL];
__device__ __nv_bfloat16 g_khi[M_ROWS * D_MODEL];
__device__ __nv_bfloat16 g_klo[M_ROWS * D_MODEL];
// V transposed per head: [b*16+h][hd 0..63][s 0..2047]
__device__ __nv_bfloat16 g_vthi[BATCH * N_HEADS * HEAD_DIM * S_LEN];
__device__ __nv_bfloat16 g_vtlo[BATCH * N_HEADS * HEAD_DIM * S_LEN];

// ---------------- bf16 mma.sync (family-agnostic, sm_80+ -> HMMA) ----------
#define MMA_BF16(d, a, b) \
    asm volatile( \
        "mma.sync.aligned.m16n8k16.row.col.f32.bf16.bf16.f32 " \
        "{%0,%1,%2,%3}, {%4,%5,%6,%7}, {%8,%9}, {%0,%1,%2,%3};" \
        : "+f"((d)[0]), "+f"((d)[1]), "+f"((d)[2]), "+f"((d)[3]) \
        : "r"((a)[0]), "r"((a)[1]), "r"((a)[2]), "r"((a)[3]), \
          "r"((b)[0]), "r"((b)[1]))

#define LDSM_X4(r0, r1, r2, r3, addr) \
    asm volatile("ldmatrix.sync.aligned.m8n8.x4.shared.b16 {%0,%1,%2,%3}, [%4];" \
        : "=r"(r0), "=r"(r1), "=r"(r2), "=r"(r3) : "r"(addr))

__device__ __forceinline__ uint32_t smem_u32(const void* p) {
    uint32_t a;
    asm("{ .reg .u64 t; cvta.to.shared.u64 t, %1; cvt.u32.u64 %0, t; }" : "=r"(a) : "l"(p));
    return a;
}

// ---------------- hi/lo bf16 conversion kernels ----------------
__global__ void conv_act_kernel(const float* __restrict__ in,
                                __nv_bfloat16* __restrict__ hi,
                                __nv_bfloat16* __restrict__ lo)
{
    size_t base = ((size_t)blockIdx.x * 256 + threadIdx.x) * 4;
    float4 v = *(const float4*)(in + base);
    __nv_bfloat16 h0 = __float2bfloat16(v.x);
    __nv_bfloat16 h1 = __float2bfloat16(v.y);
    __nv_bfloat16 h2 = __float2bfloat16(v.z);
    __nv_bfloat16 h3 = __float2bfloat16(v.w);
    ushort4 hs = { __bfloat16_as_ushort(h0), __bfloat16_as_ushort(h1),
                   __bfloat16_as_ushort(h2), __bfloat16_as_ushort(h3) };
    __nv_bfloat16 l0 = __float2bfloat16(v.x - __bfloat162float(h0));
    __nv_bfloat16 l1 = __float2bfloat16(v.y - __bfloat162float(h1));
    __nv_bfloat16 l2 = __float2bfloat16(v.z - __bfloat162float(h2));
    __nv_bfloat16 l3 = __float2bfloat16(v.w - __bfloat162float(h3));
    ushort4 ls = { __bfloat16_as_ushort(l0), __bfloat16_as_ushort(l1),
                   __bfloat16_as_ushort(l2), __bfloat16_as_ushort(l3) };
    *(ushort4*)(hi + base) = hs;
    *(ushort4*)(lo + base) = ls;
}

// W [K,N] fp32 -> Wt [N,K] bf16 hi/lo
__global__ void conv_wt_kernel(const float* __restrict__ W,
                               __nv_bfloat16* __restrict__ hi,
                               __nv_bfloat16* __restrict__ lo)
{
    __shared__ float t[32][33];
    const int x0 = blockIdx.x * 32, y0 = blockIdx.y * 32;
    const int tx = threadIdx.x, ty = threadIdx.y;
#pragma unroll
    for (int j = 0; j < 4; j++) {
        int r = ty + j * 8;
        t[r][tx] = W[(size_t)(y0 + r) * D_MODEL + x0 + tx];
    }
    __syncthreads();
#pragma unroll
    for (int j = 0; j < 4; j++) {
        int r = ty + j * 8;
        float v = t[tx][r];
        __nv_bfloat16 h = __float2bfloat16(v);
        size_t o = (size_t)(x0 + r) * D_MODEL + y0 + tx;
        hi[o] = h;
        lo[o] = __float2bfloat16(v - __bfloat162float(h));
    }
}

// ---------------- HMMA GEMM (unchanged from R8) ----------------
#define KC 64
#define TILE_BYTES (128 * KC * 2)
#define SM_AHI 0
#define SM_ALO (TILE_BYTES)
#define SM_BHI (2 * TILE_BYTES)
#define SM_BLO (3 * TILE_BYTES)
#define GEMM_SMEM (4 * TILE_BYTES)

__device__ __forceinline__ uint32_t lds_b32_sw(const char* base, int row, int kbyte) {
    int off = row * 128 + ((((kbyte >> 4) ^ (row & 7)) & 7) << 4) + (kbyte & 15);
    return *(const uint32_t*)(base + off);
}

__global__ __launch_bounds__(256) void hmma_gemm_kernel(
    const __nv_bfloat16* __restrict__ Ahi, const __nv_bfloat16* __restrict__ Alo,
    const __nv_bfloat16* __restrict__ Bhi, const __nv_bfloat16* __restrict__ Blo,
    float* __restrict__ C)
{
    extern __shared__ char smem[];
    const int tid = threadIdx.x;
    const int wid = tid >> 5, lane = tid & 31;
    const int g = lane >> 2, tg = lane & 3;
    const int mw = wid & 1, nw = wid >> 1;
    const int mBase = mw * 64, nBase = nw * 32;
    const int gM = blockIdx.y * 128, gN = blockIdx.x * 128;

    float d[4][4][4];
#pragma unroll
    for (int mt = 0; mt < 4; mt++)
#pragma unroll
        for (int nt = 0; nt < 4; nt++)
#pragma unroll
            for (int f = 0; f < 4; f++) d[mt][nt][f] = 0.0f;

    for (int k0 = 0; k0 < D_MODEL; k0 += KC) {
#pragma unroll
        for (int t = 0; t < 4; t++) {
            const __nv_bfloat16* src =
                (t == 0) ? Ahi : (t == 1) ? Alo : (t == 2) ? Bhi : Blo;
            const int gBase = (t < 2) ? gM : gN;
            char* dst = smem + t * TILE_BYTES;
#pragma unroll
            for (int it = 0; it < 4; it++) {
                int slot = it * 256 + tid;
                int row = slot >> 3, ch = slot & 7;
                uint4 val = *(const uint4*)(src + (size_t)(gBase + row) * D_MODEL
                                            + k0 + ch * 8);
                *(uint4*)(dst + row * 128 + ((ch ^ (row & 7)) << 4)) = val;
            }
        }
        __syncthreads();

        const char* sAh = smem + SM_AHI;
        const char* sAl = smem + SM_ALO;
        const char* sBh = smem + SM_BHI;
        const char* sBl = smem + SM_BLO;

#pragma unroll
        for (int ks = 0; ks < 4; ks++) {
            const int kb0 = ks * 32 + tg * 4;
            const int kb1 = kb0 + 16;
            uint32_t ah[4][4], al[4][4];
#pragma unroll
            for (int mt = 0; mt < 4; mt++) {
                int r0 = mBase + mt * 16 + g, r1 = r0 + 8;
                ah[mt][0] = lds_b32_sw(sAh, r0, kb0);
                ah[mt][1] = lds_b32_sw(sAh, r1, kb0);
                ah[mt][2] = lds_b32_sw(sAh, r0, kb1);
                ah[mt][3] = lds_b32_sw(sAh, r1, kb1);
                al[mt][0] = lds_b32_sw(sAl, r0, kb0);
                al[mt][1] = lds_b32_sw(sAl, r1, kb0);
                al[mt][2] = lds_b32_sw(sAl, r0, kb1);
                al[mt][3] = lds_b32_sw(sAl, r1, kb1);
            }
            uint32_t bh[4][2], bl[4][2];
#pragma unroll
            for (int nt = 0; nt < 4; nt++) {
                int n = nBase + nt * 8 + g;
                bh[nt][0] = lds_b32_sw(sBh, n, kb0);
                bh[nt][1] = lds_b32_sw(sBh, n, kb1);
                bl[nt][0] = lds_b32_sw(sBl, n, kb0);
                bl[nt][1] = lds_b32_sw(sBl, n, kb1);
            }
#pragma unroll
            for (int mt = 0; mt < 4; mt++)
#pragma unroll
                for (int nt = 0; nt < 4; nt++) {
                    MMA_BF16(d[mt][nt], ah[mt], bh[nt]);
                    MMA_BF16(d[mt][nt], ah[mt], bl[nt]);
                    MMA_BF16(d[mt][nt], al[mt], bh[nt]);
                }
        }
        __syncthreads();
    }

#pragma unroll
    for (int mt = 0; mt < 4; mt++) {
#pragma unroll
        for (int nt = 0; nt < 4; nt++) {
            int m = gM + mBase + mt * 16 + g;
            int n = gN + nBase + nt * 8 + tg * 2;
            float2 v0 = { d[mt][nt][0], d[mt][nt][1] };
            float2 v1 = { d[mt][nt][2], d[mt][nt][3] };
            *(float2*)(C + (size_t)m * D_MODEL + n) = v0;
            *(float2*)(C + (size_t)(m + 8) * D_MODEL + n) = v1;
        }
    }
}

// ---------------- RoPE + bf16 hi/lo split (fused) ----------------
__global__ void rope_conv_kernel(const float* __restrict__ q, const float* __restrict__ k,
                                 __nv_bfloat16* __restrict__ qhi, __nv_bfloat16* __restrict__ qlo,
                                 __nv_bfloat16* __restrict__ khi, __nv_bfloat16* __restrict__ klo)
{
    const int m = blockIdx.x;
    const int p = threadIdx.x;
    const int s = m & (S_LEN - 1);
    const int h = p >> 5, i = p & 31;

    float inv = exp2f(-((float)(2 * i) * (1.0f / 64.0f)) * 13.287712379549449f);
    float ang = (float)s * inv;
    float cs = cosf(ang), sn = sinf(ang);

    size_t i0 = (size_t)m * D_MODEL + h * HEAD_DIM + i;

    float a = q[i0], b = q[i0 + 32];
    float q0 = a * cs - b * sn;
    float q1 = b * cs + a * sn;
    a = k[i0]; b = k[i0 + 32];
    float k0 = a * cs - b * sn;
    float k1 = b * cs + a * sn;

    __nv_bfloat16 h0 = __float2bfloat16(q0), h1 = __float2bfloat16(q1);
    qhi[i0] = h0; qhi[i0 + 32] = h1;
    qlo[i0] = __float2bfloat16(q0 - __bfloat162float(h0));
    qlo[i0 + 32] = __float2bfloat16(q1 - __bfloat162float(h1));
    h0 = __float2bfloat16(k0); h1 = __float2bfloat16(k1);
    khi[i0] = h0; khi[i0 + 32] = h1;
    klo[i0] = __float2bfloat16(k0 - __bfloat162float(h0));
    klo[i0 + 32] = __float2bfloat16(k1 - __bfloat162float(h1));
}

// ---------------- V -> Vt[bh][hd][s] bf16 hi/lo (transpose + split) ----------
__global__ void vt_conv_kernel(const float* __restrict__ v,
                               __nv_bfloat16* __restrict__ vthi,
                               __nv_bfloat16* __restrict__ vtlo)
{
    __shared__ float t[32][33];
    const int s0 = blockIdx.x * 32, hd0 = blockIdx.y * 32, bh = blockIdx.z;
    const int b = bh >> 4, h = bh & 15;
    const int tx = threadIdx.x, ty = threadIdx.y;
#pragma unroll
    for (int j = 0; j < 4; j++) {
        int r = ty + j * 8;   // local s
        t[r][tx] = v[(size_t)(b * S_LEN + s0 + r) * D_MODEL + h * HEAD_DIM + hd0 + tx];
    }
    __syncthreads();
#pragma unroll
    for (int j = 0; j < 4; j++) {
        int r = ty + j * 8;   // local hd
        float val = t[tx][r];
        __nv_bfloat16 hh = __float2bfloat16(val);
        size_t o = ((size_t)bh * HEAD_DIM + hd0 + r) * S_LEN + s0 + tx;
        vthi[o] = hh;
        vtlo[o] = __float2bfloat16(val - __bfloat162float(hh));
    }
}

// ---------------- relative-position bias table ----------------
__global__ void bias_kernel(const float* __restrict__ rel_emb, float* __restrict__ bias)
{
    int idx = blockIdx.x * 256 + threadIdx.x;
    if (idx >= N_HEADS * S_LEN) return;
    int h = idx / S_LEN;
    int d = idx % S_LEN;
    int bucket;
    if (d < 16) {
        bucket = d;
    } else {
        float v = logf((float)d * (1.0f / 16.0f)) / logf(8.0f) * 16.0f;
        bucket = 16 + (int)v;
        if (bucket > 31) bucket = 31;
    }
    bias[idx] = rel_emb[bucket * N_HEADS + h];
}

// ---------------- flash attention on HMMA ----------------
// 64 q-rows per block, 128 threads (4 warps), warp w owns rows w*16..w*16+15.
// SMEM: six swizzled 64x64 bf16 tiles + bias.
#define ASM_QHI 0
#define ASM_QLO 8192
#define ASM_KHI 16384
#define ASM_KLO 24576
#define ASM_VHI 32768
#define ASM_VLO 40960
#define ASM_BIAS 49152
#define ATT_SMEM (49152 + 512)

__device__ __forceinline__ void stage_tile(char* dst, const __nv_bfloat16* src,
                                           size_t rowStride, int tid) {
#pragma unroll
    for (int it = 0; it < 4; it++) {
        int slot = it * 128 + tid;
        int row = slot >> 3, ch = slot & 7;
        uint4 val = *(const uint4*)(src + (size_t)row * rowStride + ch * 8);
        *(uint4*)(dst + row * 128 + ((ch ^ (row & 7)) << 4)) = val;
    }
}

__global__ __launch_bounds__(128) void attn_kernel(
    const __nv_bfloat16* __restrict__ qhi_g, const __nv_bfloat16* __restrict__ qlo_g,
    const __nv_bfloat16* __restrict__ khi_g, const __nv_bfloat16* __restrict__ klo_g,
    const __nv_bfloat16* __restrict__ vthi_g, const __nv_bfloat16* __restrict__ vtlo_g,
    const float* __restrict__ bias, float* __restrict__ ctx)
{
    extern __shared__ char smraw[];
    float* bias_s = (float*)(smraw + ASM_BIAS);
    const uint32_t sb = smem_u32(smraw);

    const int qb = (S_LEN / 64 - 1) - blockIdx.x;   // heavy first
    const int bh = blockIdx.y;
    const int b = bh >> 4, h = bh & 15;
    const int tid = threadIdx.x, wid = tid >> 5, lane = tid & 31;
    const int g = lane >> 2, tg = lane & 3;
    const int mBase = wid * 16;

    // per-lane ldmatrix offsets
    const int rowA = mBase + (lane & 15);
    const uint32_t offA_row = rowA * 128;
    const int a_r7 = rowA & 7;
    const int a_cb = lane >> 4;                 // k-half chunk
    const int rB0 = ((lane >> 4) << 3) + (lane & 7);
    const int b_kpar = (lane >> 3) & 1;

    // stage Q once
    stage_tile(smraw + ASM_QHI,
               qhi_g + (size_t)(b * S_LEN + qb * 64) * D_MODEL + h * HEAD_DIM,
               D_MODEL, tid);
    stage_tile(smraw + ASM_QLO,
               qlo_g + (size_t)(b * S_LEN + qb * 64) * D_MODEL + h * HEAD_DIM,
               D_MODEL, tid);

    float o[8][4];
#pragma unroll
    for (int t = 0; t < 8; t++)
#pragma unroll
        for (int j = 0; j < 4; j++) o[t][j] = 0.0f;
    float m0 = -1e30f, m1 = -1e30f, l0 = 0.0f, l1 = 0.0f;

    for (int kt = 0; kt <= qb; kt++) {
        stage_tile(smraw + ASM_KHI,
                   khi_g + (size_t)(b * S_LEN + kt * 64) * D_MODEL + h * HEAD_DIM,
                   D_MODEL, tid);
        stage_tile(smraw + ASM_KLO,
                   klo_g + (size_t)(b * S_LEN + kt * 64) * D_MODEL + h * HEAD_DIM,
                   D_MODEL, tid);
        stage_tile(smraw + ASM_VHI,
                   vthi_g + (size_t)bh * HEAD_DIM * S_LEN + kt * 64, S_LEN, tid);
        stage_tile(smraw + ASM_VLO,
                   vtlo_g + (size_t)bh * HEAD_DIM * S_LEN + kt * 64, S_LEN, tid);
        {
            int dlt = (qb - kt) * 64 - 63 + tid;
            int dcl = dlt < 0 ? 0 : (dlt > S_LEN - 1 ? S_LEN - 1 : dlt);
            bias_s[tid] = bias[h * S_LEN + dcl];
        }
        __syncthreads();

        // ---- scores: 3-term hi/lo HMMA ----
        float c[8][4];
#pragma unroll
        for (int t = 0; t < 8; t++)
#pragma unroll
            for (int j = 0; j < 4; j++) c[t][j] = 0.0f;

#pragma unroll
        for (int ks = 0; ks < 4; ks++) {
            uint32_t aoff = offA_row + ((((ks * 2 + a_cb)) ^ a_r7) << 4);
            uint32_t qh[4], ql[4];
            LDSM_X4(qh[0], qh[1], qh[2], qh[3], sb + ASM_QHI + aoff);
            LDSM_X4(ql[0], ql[1], ql[2], ql[3], sb + ASM_QLO + aoff);
#pragma unroll
            for (int ntp = 0; ntp < 4; ntp++) {
                int rowB = ntp * 16 + rB0;
                uint32_t boff = rowB * 128 + (((ks * 2 + b_kpar) ^ (rowB & 7)) << 4);
                uint32_t kh[4], kl[4];
                LDSM_X4(kh[0], kh[1], kh[2], kh[3], sb + ASM_KHI + boff);
                LDSM_X4(kl[0], kl[1], kl[2], kl[3], sb + ASM_KLO + boff);
                MMA_BF16(c[2 * ntp], qh, kh);
                MMA_BF16(c[2 * ntp], qh, kl);
                MMA_BF16(c[2 * ntp], ql, kh);
                MMA_BF16(c[2 * ntp + 1], qh, kh + 2);
                MMA_BF16(c[2 * ntp + 1], qh, kl + 2);
                MMA_BF16(c[2 * ntp + 1], ql, kh + 2);
            }
        }

        // ---- bias + scale + causal mask + in-register online softmax ----
        const bool diag = (kt == qb);
        const int rr0 = mBase + g, rr1 = rr0 + 8;
        float mx0 = -1e30f, mx1 = -1e30f;
#pragma unroll
        for (int t = 0; t < 8; t++) {
            int cbase = t * 8 + 2 * tg;
            float s0 = c[t][0] * 0.125f + bias_s[rr0 - cbase + 63];
            float s1 = c[t][1] * 0.125f + bias_s[rr0 - cbase + 62];
            float s2 = c[t][2] * 0.125f + bias_s[rr1 - cbase + 63];
            float s3 = c[t][3] * 0.125f + bias_s[rr1 - cbase + 62];
            if (diag) {
                if (cbase     > rr0) s0 = -1e9f;
                if (cbase + 1 > rr0) s1 = -1e9f;
                if (cbase     > rr1) s2 = -1e9f;
                if (cbase + 1 > rr1) s3 = -1e9f;
            }
            c[t][0] = s0; c[t][1] = s1; c[t][2] = s2; c[t][3] = s3;
            mx0 = fmaxf(mx0, fmaxf(s0, s1));
            mx1 = fmaxf(mx1, fmaxf(s2, s3));
        }
        mx0 = fmaxf(mx0, __shfl_xor_sync(0xffffffffu, mx0, 1));
        mx0 = fmaxf(mx0, __shfl_xor_sync(0xffffffffu, mx0, 2));
        mx1 = fmaxf(mx1, __shfl_xor_sync(0xffffffffu, mx1, 1));
        mx1 = fmaxf(mx1, __shfl_xor_sync(0xffffffffu, mx1, 2));
        float m0n = fmaxf(m0, mx0), m1n = fmaxf(m1, mx1);
        float corr0 = __expf(m0 - m0n), corr1 = __expf(m1 - m1n);
        m0 = m0n; m1 = m1n;

        float s0sum = 0.0f, s1sum = 0.0f;
        uint32_t phiA[8], ploA[8], phiB[8], ploB[8];
#pragma unroll
        for (int t = 0; t < 8; t++) {
            float p0 = __expf(c[t][0] - m0n), p1 = __expf(c[t][1] - m0n);
            float p2 = __expf(c[t][2] - m1n), p3 = __expf(c[t][3] - m1n);
            s0sum += p0 + p1; s1sum += p2 + p3;
            __nv_bfloat16 h0 = __float2bfloat16(p0), h1 = __float2bfloat16(p1);
            phiA[t] = ((uint32_t)__bfloat16_as_ushort(h1) << 16) | __bfloat16_as_ushort(h0);
            __nv_bfloat16 e0 = __float2bfloat16(p0 - __bfloat162float(h0));
            __nv_bfloat16 e1 = __float2bfloat16(p1 - __bfloat162float(h1));
            ploA[t] = ((uint32_t)__bfloat16_as_ushort(e1) << 16) | __bfloat16_as_ushort(e0);
            h0 = __float2bfloat16(p2); h1 = __float2bfloat16(p3);
            phiB[t] = ((uint32_t)__bfloat16_as_ushort(h1) << 16) | __bfloat16_as_ushort(h0);
            e0 = __float2bfloat16(p2 - __bfloat162float(h0));
            e1 = __float2bfloat16(p3 - __bfloat162float(h1));
            ploB[t] = ((uint32_t)__bfloat16_as_ushort(e1) << 16) | __bfloat16_as_ushort(e0);
        }
        s0sum += __shfl_xor_sync(0xffffffffu, s0sum, 1);
        s0sum += __shfl_xor_sync(0xffffffffu, s0sum, 2);
        s1sum += __shfl_xor_sync(0xffffffffu, s1sum, 1);
        s1sum += __shfl_xor_sync(0xffffffffu, s1sum, 2);
        l0 = l0 * corr0 + s0sum;
        l1 = l1 * corr1 + s1sum;
#pragma unroll
        for (int t = 0; t < 8; t++) {
            o[t][0] *= corr0; o[t][1] *= corr0;
            o[t][2] *= corr1; o[t][3] *= corr1;
        }

        // ---- PV: P fragments come straight from score C fragments ----
#pragma unroll
        for (int kt2 = 0; kt2 < 4; kt2++) {
            uint32_t pah[4] = { phiA[2 * kt2], phiB[2 * kt2],
                                phiA[2 * kt2 + 1], phiB[2 * kt2 + 1] };
            uint32_t pal[4] = { ploA[2 * kt2], ploB[2 * kt2],
                                ploA[2 * kt2 + 1], ploB[2 * kt2 + 1] };
#pragma unroll
            for (int ntp = 0; ntp < 4; ntp++) {
                int rowB = ntp * 16 + rB0;
                uint32_t boff = rowB * 128 + (((kt2 * 2 + b_kpar) ^ (rowB & 7)) << 4);
                uint32_t vh[4], vl[4];
                LDSM_X4(vh[0], vh[1], vh[2], vh[3], sb + ASM_VHI + boff);
                LDSM_X4(vl[0], vl[1], vl[2], vl[3], sb + ASM_VLO + boff);
                MMA_BF16(o[2 * ntp], pah, vh);
                MMA_BF16(o[2 * ntp], pah, vl);
                MMA_BF16(o[2 * ntp], pal, vh);
                MMA_BF16(o[2 * ntp + 1], pah, vh + 2);
                MMA_BF16(o[2 * ntp + 1], pah, vl + 2);
                MMA_BF16(o[2 * ntp + 1], pal, vh + 2);
            }
        }
        __syncthreads();
    }

    // ---- epilogue ----
    float inv0 = 1.0f / l0, inv1 = 1.0f / l1;
    const int row0 = b * S_LEN + qb * 64 + mBase + g;
    const int row1 = row0 + 8;
#pragma unroll
    for (int t = 0; t < 8; t++) {
        int col = h * HEAD_DIM + t * 8 + 2 * tg;
        float2 v0 = { o[t][0] * inv0, o[t][1] * inv0 };
        float2 v1 = { o[t][2] * inv1, o[t][3] * inv1 };
        *(float2*)(ctx + (size_t)row0 * D_MODEL + col) = v0;
        *(float2*)(ctx + (size_t)row1 * D_MODEL + col) = v1;
    }
}

// ---------------- launcher ----------------
extern "C" void kernel_launch(void* const* d_in, const int* in_sizes, int n_in,
                              void* d_out, int out_size)
{
    const float* x   = (const float*)d_in[0];
    const float* Wq  = (const float*)d_in[1];
    const float* Wk  = (const float*)d_in[2];
    const float* Wv  = (const float*)d_in[3];
    const float* Wo  = (const float*)d_in[4];
    const float* rel = (const float*)d_in[5];

    float *qp, *kp, *vp, *cp, *bp;
    __nv_bfloat16 *ahi, *alo, *whi, *wlo;
    __nv_bfloat16 *qhi, *qlo, *khi, *klo, *vthi, *vtlo;
    cudaGetSymbolAddress((void**)&qp, g_q);
    cudaGetSymbolAddress((void**)&kp, g_k);
    cudaGetSymbolAddress((void**)&vp, g_v);
    cudaGetSymbolAddress((void**)&cp, g_ctx);
    cudaGetSymbolAddress((void**)&bp, g_bias);
    cudaGetSymbolAddress((void**)&ahi, g_ahi);
    cudaGetSymbolAddress((void**)&alo, g_alo);
    cudaGetSymbolAddress((void**)&whi, g_whi);
    cudaGetSymbolAddress((void**)&wlo, g_wlo);
    cudaGetSymbolAddress((void**)&qhi, g_qhi);
    cudaGetSymbolAddress((void**)&qlo, g_qlo);
    cudaGetSymbolAddress((void**)&khi, g_khi);
    cudaGetSymbolAddress((void**)&klo, g_klo);
    cudaGetSymbolAddress((void**)&vthi, g_vthi);
    cudaGetSymbolAddress((void**)&vtlo, g_vtlo);

    const size_t WSTRIDE = (size_t)D_MODEL * D_MODEL;
    const float* Ws[4] = {Wq, Wk, Wv, Wo};

    // conversions
    conv_act_kernel<<<M_ROWS * D_MODEL / (256 * 4), 256>>>(x, ahi, alo);
    for (int w = 0; w < 4; w++)
        conv_wt_kernel<<<dim3(32, 32), dim3(32, 8)>>>(Ws[w], whi + w * WSTRIDE,
                                                      wlo + w * WSTRIDE);
    bias_kernel<<<(N_HEADS * S_LEN + 255) / 256, 256>>>(rel, bp);

    // QKV projections on HMMA tensor cores
    cudaFuncSetAttribute(hmma_gemm_kernel, cudaFuncAttributeMaxDynamicSharedMemorySize,
                         GEMM_SMEM);
    dim3 gg(D_MODEL / 128, M_ROWS / 128);
    hmma_gemm_kernel<<<gg, 256, GEMM_SMEM>>>(ahi, alo, whi + 0 * WSTRIDE,
                                             wlo + 0 * WSTRIDE, qp);
    hmma_gemm_kernel<<<gg, 256, GEMM_SMEM>>>(ahi, alo, whi + 1 * WSTRIDE,
                                             wlo + 1 * WSTRIDE, kp);
    hmma_gemm_kernel<<<gg, 256, GEMM_SMEM>>>(ahi, alo, whi + 2 * WSTRIDE,
                                             wlo + 2 * WSTRIDE, vp);

    // RoPE fused with bf16 split; V transpose+split
    rope_conv_kernel<<<M_ROWS, 512>>>(qp, kp, qhi, qlo, khi, klo);
    vt_conv_kernel<<<dim3(S_LEN / 32, HEAD_DIM / 32, BATCH * N_HEADS),
                     dim3(32, 8)>>>(vp, vthi, vtlo);

    // attention on HMMA
    cudaFuncSetAttribute(attn_kernel, cudaFuncAttributeMaxDynamicSharedMemorySize,
                         ATT_SMEM);
    attn_kernel<<<dim3(S_LEN / 64, BATCH * N_HEADS), 128, ATT_SMEM>>>(
        qhi, qlo, khi, klo, vthi, vtlo, bp, cp);

    // output projection
    conv_act_kernel<<<M_ROWS * D_MODEL / (256 * 4), 256>>>(cp, ahi, alo);
    hmma_gemm_kernel<<<gg, 256, GEMM_SMEM>>>(ahi, alo, whi + 3 * WSTRIDE,
                                             wlo + 3 * WSTRIDE, (float*)d_out);
}

// round 10
// speedup vs baseline: 2.6075x; 1.0654x over previous
#include <cuda_runtime.h>
#include <cuda_bf16.h>
#include <math.h>
#include <stdint.h>

#define S_LEN   2048
#define D_MODEL 1024
#define N_HEADS 16
#define HEAD_DIM 64
#define BATCH   2
#define M_ROWS  (BATCH * S_LEN)   // 4096

// ---------------- device scratch (no allocations allowed) ----------------
__device__ float g_q[M_ROWS * D_MODEL];
__device__ float g_k[M_ROWS * D_MODEL];
__device__ float g_v[M_ROWS * D_MODEL];
__device__ float g_bias[N_HEADS * S_LEN];
__device__ __nv_bfloat16 g_ahi[M_ROWS * D_MODEL];
__device__ __nv_bfloat16 g_alo[M_ROWS * D_MODEL];
__device__ __nv_bfloat16 g_whi[4][D_MODEL * D_MODEL];   // transposed [N][K]
__device__ __nv_bfloat16 g_wlo[4][D_MODEL * D_MODEL];
__device__ __nv_bfloat16 g_qhi[M_ROWS * D_MODEL];
__device__ __nv_bfloat16 g_qlo[M_ROWS * D_MODEL];
__device__ __nv_bfloat16 g_khi[M_ROWS * D_MODEL];
__device__ __nv_bfloat16 g_klo[M_ROWS * D_MODEL];
__device__ __nv_bfloat16 g_vthi[BATCH * N_HEADS * HEAD_DIM * S_LEN];
__device__ __nv_bfloat16 g_vtlo[BATCH * N_HEADS * HEAD_DIM * S_LEN];

// ---------------- bf16 mma.sync / ldmatrix / cp.async helpers ----------------
#define MMA_BF16(d, a, b) \
    asm volatile( \
        "mma.sync.aligned.m16n8k16.row.col.f32.bf16.bf16.f32 " \
        "{%0,%1,%2,%3}, {%4,%5,%6,%7}, {%8,%9}, {%0,%1,%2,%3};" \
        : "+f"((d)[0]), "+f"((d)[1]), "+f"((d)[2]), "+f"((d)[3]) \
        : "r"((a)[0]), "r"((a)[1]), "r"((a)[2]), "r"((a)[3]), \
          "r"((b)[0]), "r"((b)[1]))

#define LDSM_X4(r0, r1, r2, r3, addr) \
    asm volatile("ldmatrix.sync.aligned.m8n8.x4.shared.b16 {%0,%1,%2,%3}, [%4];" \
        : "=r"(r0), "=r"(r1), "=r"(r2), "=r"(r3) : "r"(addr))

__device__ __forceinline__ uint32_t smem_u32(const void* p) {
    uint32_t a;
    asm("{ .reg .u64 t; cvta.to.shared.u64 t, %1; cvt.u32.u64 %0, t; }" : "=r"(a) : "l"(p));
    return a;
}
__device__ __forceinline__ void cp_async16(uint32_t dst, const void* src) {
    asm volatile("cp.async.cg.shared.global [%0], [%1], 16;" :: "r"(dst), "l"(src));
}
#define CP_COMMIT() asm volatile("cp.async.commit_group;")
#define CP_WAIT(n)  asm volatile("cp.async.wait_group %0;" :: "n"(n))

// ---------------- hi/lo bf16 conversion kernels ----------------
__global__ void conv_act_kernel(const float* __restrict__ in,
                                __nv_bfloat16* __restrict__ hi,
                                __nv_bfloat16* __restrict__ lo)
{
    size_t base = ((size_t)blockIdx.x * 256 + threadIdx.x) * 4;
    float4 v = *(const float4*)(in + base);
    __nv_bfloat16 h0 = __float2bfloat16(v.x);
    __nv_bfloat16 h1 = __float2bfloat16(v.y);
    __nv_bfloat16 h2 = __float2bfloat16(v.z);
    __nv_bfloat16 h3 = __float2bfloat16(v.w);
    ushort4 hs = { __bfloat16_as_ushort(h0), __bfloat16_as_ushort(h1),
                   __bfloat16_as_ushort(h2), __bfloat16_as_ushort(h3) };
    __nv_bfloat16 l0 = __float2bfloat16(v.x - __bfloat162float(h0));
    __nv_bfloat16 l1 = __float2bfloat16(v.y - __bfloat162float(h1));
    __nv_bfloat16 l2 = __float2bfloat16(v.z - __bfloat162float(h2));
    __nv_bfloat16 l3 = __float2bfloat16(v.w - __bfloat162float(h3));
    ushort4 ls = { __bfloat16_as_ushort(l0), __bfloat16_as_ushort(l1),
                   __bfloat16_as_ushort(l2), __bfloat16_as_ushort(l3) };
    *(ushort4*)(hi + base) = hs;
    *(ushort4*)(lo + base) = ls;
}

// W [K,N] fp32 -> Wt [N,K] bf16 hi/lo
__global__ void conv_wt_kernel(const float* __restrict__ W,
                               __nv_bfloat16* __restrict__ hi,
                               __nv_bfloat16* __restrict__ lo)
{
    __shared__ float t[32][33];
    const int x0 = blockIdx.x * 32, y0 = blockIdx.y * 32;
    const int tx = threadIdx.x, ty = threadIdx.y;
#pragma unroll
    for (int j = 0; j < 4; j++) {
        int r = ty + j * 8;
        t[r][tx] = W[(size_t)(y0 + r) * D_MODEL + x0 + tx];
    }
    __syncthreads();
#pragma unroll
    for (int j = 0; j < 4; j++) {
        int r = ty + j * 8;
        float v = t[tx][r];
        __nv_bfloat16 h = __float2bfloat16(v);
        size_t o = (size_t)(x0 + r) * D_MODEL + y0 + tx;
        hi[o] = h;
        lo[o] = __float2bfloat16(v - __bfloat162float(h));
    }
}

// ---------------- pipelined HMMA GEMM ----------------
// Tiles per stage: A-packed [128 rows][hi 64B | lo 64B] = 16KB, B-packed same.
// 2 stages, K-stage = 32. Xor swizzle on 16B chunks: ch ^= row&7.
#define KS2 32
#define PTILE 16384                       // one packed tile
#define STAGE_BYTES (2 * PTILE)           // A + B per stage
#define GEMM_SMEM (2 * STAGE_BYTES)       // 65536

__device__ __forceinline__ void gemm_prefetch(
    uint32_t sbase, int stage,
    const __nv_bfloat16* Ahi, const __nv_bfloat16* Alo,
    const __nv_bfloat16* Bhi, const __nv_bfloat16* Blo,
    int gM, int gN, int k0, int tid)
{
    uint32_t stg = sbase + stage * STAGE_BYTES;
#pragma unroll
    for (int it = 0; it < 8; it++) {
        int slot = it * 256 + tid;            // 0..2047
        int tb = slot >> 10;                  // 0: A, 1: B
        int r  = (slot >> 3) & 127;
        int ch = slot & 7;
        const __nv_bfloat16* src = tb
            ? ((ch < 4) ? Bhi : Blo) + (size_t)(gN + r) * D_MODEL
            : ((ch < 4) ? Ahi : Alo) + (size_t)(gM + r) * D_MODEL;
        src += k0 + (ch & 3) * 8;
        uint32_t dst = stg + tb * PTILE + r * 128 + ((ch ^ (r & 7)) << 4);
        cp_async16(dst, src);
    }
}

__global__ __launch_bounds__(256) void hmma_gemm_kernel(
    const __nv_bfloat16* __restrict__ Ahi, const __nv_bfloat16* __restrict__ Alo,
    const __nv_bfloat16* __restrict__ Bhi, const __nv_bfloat16* __restrict__ Blo,
    float* __restrict__ C)
{
    extern __shared__ char smem[];
    const uint32_t sbase = smem_u32(smem);
    const int tid = threadIdx.x;
    const int wid = tid >> 5, lane = tid & 31;
    const int g = lane >> 2, tg = lane & 3;
    const int mw = wid & 1, nw = wid >> 1;
    const int mBase = mw * 64, nBase = nw * 32;
    const int gM = blockIdx.y * 128, gN = blockIdx.x * 128;

    // ldmatrix lane addressing (same mapping validated in attention kernel)
    const int aRow = lane & 15;               // + mBase + mt*16
    const int a_cb = lane >> 4;               // k-half chunk parity
    const int rB0 = ((lane >> 4) << 3) + (lane & 7);
    const int b_kpar = (lane >> 3) & 1;

    float d[4][4][4];
#pragma unroll
    for (int mt = 0; mt < 4; mt++)
#pragma unroll
        for (int nt = 0; nt < 4; nt++)
#pragma unroll
            for (int f = 0; f < 4; f++) d[mt][nt][f] = 0.0f;

    gemm_prefetch(sbase, 0, Ahi, Alo, Bhi, Blo, gM, gN, 0, tid);
    CP_COMMIT();

    const int NITER = D_MODEL / KS2;          // 32
    for (int itk = 0; itk < NITER; itk++) {
        if (itk + 1 < NITER) {
            gemm_prefetch(sbase, (itk + 1) & 1, Ahi, Alo, Bhi, Blo,
                          gM, gN, (itk + 1) * KS2, tid);
            CP_COMMIT();
            CP_WAIT(1);
        } else {
            CP_WAIT(0);
        }
        __syncthreads();

        const uint32_t stA = sbase + (itk & 1) * STAGE_BYTES;
        const uint32_t stB = stA + PTILE;

#pragma unroll
        for (int ks = 0; ks < 2; ks++) {
            const int chHi = ks * 2 + a_cb;            // 0..3
            uint32_t ah[4][4], al[4][4];
#pragma unroll
            for (int mt = 0; mt < 4; mt++) {
                int rA = mBase + mt * 16 + aRow;
                uint32_t base = stA + rA * 128;
                int r7 = rA & 7;
                LDSM_X4(ah[mt][0], ah[mt][1], ah[mt][2], ah[mt][3],
                        base + ((chHi ^ r7) << 4));
                LDSM_X4(al[mt][0], al[mt][1], al[mt][2], al[mt][3],
                        base + (((chHi + 4) ^ r7) << 4));
            }
#pragma unroll
            for (int ntp = 0; ntp < 2; ntp++) {
                int rB = nBase + ntp * 16 + rB0;
                uint32_t base = stB + rB * 128;
                int r7 = rB & 7;
                int chB = ks * 2 + b_kpar;
                uint32_t bh[4], bl[4];
                LDSM_X4(bh[0], bh[1], bh[2], bh[3], base + ((chB ^ r7) << 4));
                LDSM_X4(bl[0], bl[1], bl[2], bl[3], base + (((chB + 4) ^ r7) << 4));
#pragma unroll
                for (int mt = 0; mt < 4; mt++) {
                    MMA_BF16(d[mt][2 * ntp], ah[mt], bh);
                    MMA_BF16(d[mt][2 * ntp], ah[mt], bl);
                    MMA_BF16(d[mt][2 * ntp], al[mt], bh);
                    MMA_BF16(d[mt][2 * ntp + 1], ah[mt], bh + 2);
                    MMA_BF16(d[mt][2 * ntp + 1], ah[mt], bl + 2);
                    MMA_BF16(d[mt][2 * ntp + 1], al[mt], bh + 2);
                }
            }
        }
        __syncthreads();
    }

#pragma unroll
    for (int mt = 0; mt < 4; mt++) {
#pragma unroll
        for (int nt = 0; nt < 4; nt++) {
            int m = gM + mBase + mt * 16 + g;
            int n = gN + nBase + nt * 8 + tg * 2;
            float2 v0 = { d[mt][nt][0], d[mt][nt][1] };
            float2 v1 = { d[mt][nt][2], d[mt][nt][3] };
            *(float2*)(C + (size_t)m * D_MODEL + n) = v0;
            *(float2*)(C + (size_t)(m + 8) * D_MODEL + n) = v1;
        }
    }
}

// ---------------- RoPE + bf16 hi/lo split (fused) ----------------
__global__ void rope_conv_kernel(const float* __restrict__ q, const float* __restrict__ k,
                                 __nv_bfloat16* __restrict__ qhi, __nv_bfloat16* __restrict__ qlo,
                                 __nv_bfloat16* __restrict__ khi, __nv_bfloat16* __restrict__ klo)
{
    const int m = blockIdx.x;
    const int p = threadIdx.x;
    const int s = m & (S_LEN - 1);
    const int h = p >> 5, i = p & 31;

    float inv = exp2f(-((float)(2 * i) * (1.0f / 64.0f)) * 13.287712379549449f);
    float ang = (float)s * inv;
    float cs = cosf(ang), sn = sinf(ang);

    size_t i0 = (size_t)m * D_MODEL + h * HEAD_DIM + i;

    float a = q[i0], b = q[i0 + 32];
    float q0 = a * cs - b * sn;
    float q1 = b * cs + a * sn;
    a = k[i0]; b = k[i0 + 32];
    float k0 = a * cs - b * sn;
    float k1 = b * cs + a * sn;

    __nv_bfloat16 h0 = __float2bfloat16(q0), h1 = __float2bfloat16(q1);
    qhi[i0] = h0; qhi[i0 + 32] = h1;
    qlo[i0] = __float2bfloat16(q0 - __bfloat162float(h0));
    qlo[i0 + 32] = __float2bfloat16(q1 - __bfloat162float(h1));
    h0 = __float2bfloat16(k0); h1 = __float2bfloat16(k1);
    khi[i0] = h0; khi[i0 + 32] = h1;
    klo[i0] = __float2bfloat16(k0 - __bfloat162float(h0));
    klo[i0 + 32] = __float2bfloat16(k1 - __bfloat162float(h1));
}

// ---------------- V -> Vt[bh][hd][s] bf16 hi/lo ----------------
__global__ void vt_conv_kernel(const float* __restrict__ v,
                               __nv_bfloat16* __restrict__ vthi,
                               __nv_bfloat16* __restrict__ vtlo)
{
    __shared__ float t[32][33];
    const int s0 = blockIdx.x * 32, hd0 = blockIdx.y * 32, bh = blockIdx.z;
    const int b = bh >> 4, h = bh & 15;
    const int tx = threadIdx.x, ty = threadIdx.y;
#pragma unroll
    for (int j = 0; j < 4; j++) {
        int r = ty + j * 8;
        t[r][tx] = v[(size_t)(b * S_LEN + s0 + r) * D_MODEL + h * HEAD_DIM + hd0 + tx];
    }
    __syncthreads();
#pragma unroll
    for (int j = 0; j < 4; j++) {
        int r = ty + j * 8;
        float val = t[tx][r];
        __nv_bfloat16 hh = __float2bfloat16(val);
        size_t o = ((size_t)bh * HEAD_DIM + hd0 + r) * S_LEN + s0 + tx;
        vthi[o] = hh;
        vtlo[o] = __float2bfloat16(val - __bfloat162float(hh));
    }
}

// ---------------- relative-position bias table ----------------
__global__ void bias_kernel(const float* __restrict__ rel_emb, float* __restrict__ bias)
{
    int idx = blockIdx.x * 256 + threadIdx.x;
    if (idx >= N_HEADS * S_LEN) return;
    int h = idx / S_LEN;
    int d = idx % S_LEN;
    int bucket;
    if (d < 16) {
        bucket = d;
    } else {
        float v = logf((float)d * (1.0f / 16.0f)) / logf(8.0f) * 16.0f;
        bucket = 16 + (int)v;
        if (bucket > 31) bucket = 31;
    }
    bias[idx] = rel_emb[bucket * N_HEADS + h];
}

// ---------------- flash attention on HMMA (R9, epilogue -> bf16 hi/lo) ------
#define ASM_QHI 0
#define ASM_QLO 8192
#define ASM_KHI 16384
#define ASM_KLO 24576
#define ASM_VHI 32768
#define ASM_VLO 40960
#define ASM_BIAS 49152
#define ATT_SMEM (49152 + 512)

__device__ __forceinline__ void stage_tile(char* dst, const __nv_bfloat16* src,
                                           size_t rowStride, int tid) {
#pragma unroll
    for (int it = 0; it < 4; it++) {
        int slot = it * 128 + tid;
        int row = slot >> 3, ch = slot & 7;
        uint4 val = *(const uint4*)(src + (size_t)row * rowStride + ch * 8);
        *(uint4*)(dst + row * 128 + ((ch ^ (row & 7)) << 4)) = val;
    }
}

__global__ __launch_bounds__(128) void attn_kernel(
    const __nv_bfloat16* __restrict__ qhi_g, const __nv_bfloat16* __restrict__ qlo_g,
    const __nv_bfloat16* __restrict__ khi_g, const __nv_bfloat16* __restrict__ klo_g,
    const __nv_bfloat16* __restrict__ vthi_g, const __nv_bfloat16* __restrict__ vtlo_g,
    const float* __restrict__ bias,
    __nv_bfloat16* __restrict__ chi, __nv_bfloat16* __restrict__ clo)
{
    extern __shared__ char smraw[];
    float* bias_s = (float*)(smraw + ASM_BIAS);
    const uint32_t sb = smem_u32(smraw);

    const int qb = (S_LEN / 64 - 1) - blockIdx.x;
    const int bh = blockIdx.y;
    const int b = bh >> 4, h = bh & 15;
    const int tid = threadIdx.x, wid = tid >> 5, lane = tid & 31;
    const int g = lane >> 2, tg = lane & 3;
    const int mBase = wid * 16;

    const int rowA = mBase + (lane & 15);
    const uint32_t offA_row = rowA * 128;
    const int a_r7 = rowA & 7;
    const int a_cb = lane >> 4;
    const int rB0 = ((lane >> 4) << 3) + (lane & 7);
    const int b_kpar = (lane >> 3) & 1;

    stage_tile(smraw + ASM_QHI,
               qhi_g + (size_t)(b * S_LEN + qb * 64) * D_MODEL + h * HEAD_DIM,
               D_MODEL, tid);
    stage_tile(smraw + ASM_QLO,
               qlo_g + (size_t)(b * S_LEN + qb * 64) * D_MODEL + h * HEAD_DIM,
               D_MODEL, tid);

    float o[8][4];
#pragma unroll
    for (int t = 0; t < 8; t++)
#pragma unroll
        for (int j = 0; j < 4; j++) o[t][j] = 0.0f;
    float m0 = -1e30f, m1 = -1e30f, l0 = 0.0f, l1 = 0.0f;

    for (int kt = 0; kt <= qb; kt++) {
        stage_tile(smraw + ASM_KHI,
                   khi_g + (size_t)(b * S_LEN + kt * 64) * D_MODEL + h * HEAD_DIM,
                   D_MODEL, tid);
        stage_tile(smraw + ASM_KLO,
                   klo_g + (size_t)(b * S_LEN + kt * 64) * D_MODEL + h * HEAD_DIM,
                   D_MODEL, tid);
        stage_tile(smraw + ASM_VHI,
                   vthi_g + (size_t)bh * HEAD_DIM * S_LEN + kt * 64, S_LEN, tid);
        stage_tile(smraw + ASM_VLO,
                   vtlo_g + (size_t)bh * HEAD_DIM * S_LEN + kt * 64, S_LEN, tid);
        {
            int dlt = (qb - kt) * 64 - 63 + tid;
            int dcl = dlt < 0 ? 0 : (dlt > S_LEN - 1 ? S_LEN - 1 : dlt);
            bias_s[tid] = bias[h * S_LEN + dcl];
        }
        __syncthreads();

        float c[8][4];
#pragma unroll
        for (int t = 0; t < 8; t++)
#pragma unroll
            for (int j = 0; j < 4; j++) c[t][j] = 0.0f;

#pragma unroll
        for (int ks = 0; ks < 4; ks++) {
            uint32_t aoff = offA_row + ((((ks * 2 + a_cb)) ^ a_r7) << 4);
            uint32_t qh[4], ql[4];
            LDSM_X4(qh[0], qh[1], qh[2], qh[3], sb + ASM_QHI + aoff);
            LDSM_X4(ql[0], ql[1], ql[2], ql[3], sb + ASM_QLO + aoff);
#pragma unroll
            for (int ntp = 0; ntp < 4; ntp++) {
                int rowB = ntp * 16 + rB0;
                uint32_t boff = rowB * 128 + (((ks * 2 + b_kpar) ^ (rowB & 7)) << 4);
                uint32_t kh[4], kl[4];
                LDSM_X4(kh[0], kh[1], kh[2], kh[3], sb + ASM_KHI + boff);
                LDSM_X4(kl[0], kl[1], kl[2], kl[3], sb + ASM_KLO + boff);
                MMA_BF16(c[2 * ntp], qh, kh);
                MMA_BF16(c[2 * ntp], qh, kl);
                MMA_BF16(c[2 * ntp], ql, kh);
                MMA_BF16(c[2 * ntp + 1], qh, kh + 2);
                MMA_BF16(c[2 * ntp + 1], qh, kl + 2);
                MMA_BF16(c[2 * ntp + 1], ql, kh + 2);
            }
        }

        const bool diag = (kt == qb);
        const int rr0 = mBase + g, rr1 = rr0 + 8;
        float mx0 = -1e30f, mx1 = -1e30f;
#pragma unroll
        for (int t = 0; t < 8; t++) {
            int cbase = t * 8 + 2 * tg;
            float s0 = c[t][0] * 0.125f + bias_s[rr0 - cbase + 63];
            float s1 = c[t][1] * 0.125f + bias_s[rr0 - cbase + 62];
            float s2 = c[t][2] * 0.125f + bias_s[rr1 - cbase + 63];
            float s3 = c[t][3] * 0.125f + bias_s[rr1 - cbase + 62];
            if (diag) {
                if (cbase     > rr0) s0 = -1e9f;
                if (cbase + 1 > rr0) s1 = -1e9f;
                if (cbase     > rr1) s2 = -1e9f;
                if (cbase + 1 > rr1) s3 = -1e9f;
            }
            c[t][0] = s0; c[t][1] = s1; c[t][2] = s2; c[t][3] = s3;
            mx0 = fmaxf(mx0, fmaxf(s0, s1));
            mx1 = fmaxf(mx1, fmaxf(s2, s3));
        }
        mx0 = fmaxf(mx0, __shfl_xor_sync(0xffffffffu, mx0, 1));
        mx0 = fmaxf(mx0, __shfl_xor_sync(0xffffffffu, mx0, 2));
        mx1 = fmaxf(mx1, __shfl_xor_sync(0xffffffffu, mx1, 1));
        mx1 = fmaxf(mx1, __shfl_xor_sync(0xffffffffu, mx1, 2));
        float m0n = fmaxf(m0, mx0), m1n = fmaxf(m1, mx1);
        float corr0 = __expf(m0 - m0n), corr1 = __expf(m1 - m1n);
        m0 = m0n; m1 = m1n;

        float s0sum = 0.0f, s1sum = 0.0f;
        uint32_t phiA[8], ploA[8], phiB[8], ploB[8];
#pragma unroll
        for (int t = 0; t < 8; t++) {
            float p0 = __expf(c[t][0] - m0n), p1 = __expf(c[t][1] - m0n);
            float p2 = __expf(c[t][2] - m1n), p3 = __expf(c[t][3] - m1n);
            s0sum += p0 + p1; s1sum += p2 + p3;
            __nv_bfloat16 h0 = __float2bfloat16(p0), h1 = __float2bfloat16(p1);
            phiA[t] = ((uint32_t)__bfloat16_as_ushort(h1) << 16) | __bfloat16_as_ushort(h0);
            __nv_bfloat16 e0 = __float2bfloat16(p0 - __bfloat162float(h0));
            __nv_bfloat16 e1 = __float2bfloat16(p1 - __bfloat162float(h1));
            ploA[t] = ((uint32_t)__bfloat16_as_ushort(e1) << 16) | __bfloat16_as_ushort(e0);
            h0 = __float2bfloat16(p2); h1 = __float2bfloat16(p3);
            phiB[t] = ((uint32_t)__bfloat16_as_ushort(h1) << 16) | __bfloat16_as_ushort(h0);
            e0 = __float2bfloat16(p2 - __bfloat162float(h0));
            e1 = __float2bfloat16(p3 - __bfloat162float(h1));
            ploB[t] = ((uint32_t)__bfloat16_as_ushort(e1) << 16) | __bfloat16_as_ushort(e0);
        }
        s0sum += __shfl_xor_sync(0xffffffffu, s0sum, 1);
        s0sum += __shfl_xor_sync(0xffffffffu, s0sum, 2);
        s1sum += __shfl_xor_sync(0xffffffffu, s1sum, 1);
        s1sum += __shfl_xor_sync(0xffffffffu, s1sum, 2);
        l0 = l0 * corr0 + s0sum;
        l1 = l1 * corr1 + s1sum;
#pragma unroll
        for (int t = 0; t < 8; t++) {
            o[t][0] *= corr0; o[t][1] *= corr0;
            o[t][2] *= corr1; o[t][3] *= corr1;
        }

#pragma unroll
        for (int kt2 = 0; kt2 < 4; kt2++) {
            uint32_t pah[4] = { phiA[2 * kt2], phiB[2 * kt2],
                                phiA[2 * kt2 + 1], phiB[2 * kt2 + 1] };
            uint32_t pal[4] = { ploA[2 * kt2], ploB[2 * kt2],
                                ploA[2 * kt2 + 1], ploB[2 * kt2 + 1] };
#pragma unroll
            for (int ntp = 0; ntp < 4; ntp++) {
                int rowB = ntp * 16 + rB0;
                uint32_t boff = rowB * 128 + (((kt2 * 2 + b_kpar) ^ (rowB & 7)) << 4);
                uint32_t vh[4], vl[4];
                LDSM_X4(vh[0], vh[1], vh[2], vh[3], sb + ASM_VHI + boff);
                LDSM_X4(vl[0], vl[1], vl[2], vl[3], sb + ASM_VLO + boff);
                MMA_BF16(o[2 * ntp], pah, vh);
                MMA_BF16(o[2 * ntp], pah, vl);
                MMA_BF16(o[2 * ntp], pal, vh);
                MMA_BF16(o[2 * ntp + 1], pah, vh + 2);
                MMA_BF16(o[2 * ntp + 1], pah, vl + 2);
                MMA_BF16(o[2 * ntp + 1], pal, vh + 2);
            }
        }
        __syncthreads();
    }

    // ---- epilogue: normalize and emit bf16 hi/lo directly ----
    float inv0 = 1.0f / l0, inv1 = 1.0f / l1;
    const int row0 = b * S_LEN + qb * 64 + mBase + g;
    const int row1 = row0 + 8;
#pragma unroll
    for (int t = 0; t < 8; t++) {
        int col = h * HEAD_DIM + t * 8 + 2 * tg;
        float v0 = o[t][0] * inv0, v1 = o[t][1] * inv0;
        float v2 = o[t][2] * inv1, v3 = o[t][3] * inv1;
        __nv_bfloat16 h0 = __float2bfloat16(v0), h1 = __float2bfloat16(v1);
        __nv_bfloat16 h2 = __float2bfloat16(v2), h3 = __float2bfloat16(v3);
        uint32_t hi01 = ((uint32_t)__bfloat16_as_ushort(h1) << 16) | __bfloat16_as_ushort(h0);
        uint32_t hi23 = ((uint32_t)__bfloat16_as_ushort(h3) << 16) | __bfloat16_as_ushort(h2);
        __nv_bfloat16 e0 = __float2bfloat16(v0 - __bfloat162float(h0));
        __nv_bfloat16 e1 = __float2bfloat16(v1 - __bfloat162float(h1));
        __nv_bfloat16 e2 = __float2bfloat16(v2 - __bfloat162float(h2));
        __nv_bfloat16 e3 = __float2bfloat16(v3 - __bfloat162float(h3));
        uint32_t lo01 = ((uint32_t)__bfloat16_as_ushort(e1) << 16) | __bfloat16_as_ushort(e0);
        uint32_t lo23 = ((uint32_t)__bfloat16_as_ushort(e3) << 16) | __bfloat16_as_ushort(e2);
        *(uint32_t*)(chi + (size_t)row0 * D_MODEL + col) = hi01;
        *(uint32_t*)(chi + (size_t)row1 * D_MODEL + col) = hi23;
        *(uint32_t*)(clo + (size_t)row0 * D_MODEL + col) = lo01;
        *(uint32_t*)(clo + (size_t)row1 * D_MODEL + col) = lo23;
    }
}

// ---------------- launcher ----------------
extern "C" void kernel_launch(void* const* d_in, const int* in_sizes, int n_in,
                              void* d_out, int out_size)
{
    const float* x   = (const float*)d_in[0];
    const float* Wq  = (const float*)d_in[1];
    const float* Wk  = (const float*)d_in[2];
    const float* Wv  = (const float*)d_in[3];
    const float* Wo  = (const float*)d_in[4];
    const float* rel = (const float*)d_in[5];

    float *qp, *kp, *vp, *bp;
    __nv_bfloat16 *ahi, *alo, *whi, *wlo;
    __nv_bfloat16 *qhi, *qlo, *khi, *klo, *vthi, *vtlo;
    cudaGetSymbolAddress((void**)&qp, g_q);
    cudaGetSymbolAddress((void**)&kp, g_k);
    cudaGetSymbolAddress((void**)&vp, g_v);
    cudaGetSymbolAddress((void**)&bp, g_bias);
    cudaGetSymbolAddress((void**)&ahi, g_ahi);
    cudaGetSymbolAddress((void**)&alo, g_alo);
    cudaGetSymbolAddress((void**)&whi, g_whi);
    cudaGetSymbolAddress((void**)&wlo, g_wlo);
    cudaGetSymbolAddress((void**)&qhi, g_qhi);
    cudaGetSymbolAddress((void**)&qlo, g_qlo);
    cudaGetSymbolAddress((void**)&khi, g_khi);
    cudaGetSymbolAddress((void**)&klo, g_klo);
    cudaGetSymbolAddress((void**)&vthi, g_vthi);
    cudaGetSymbolAddress((void**)&vtlo, g_vtlo);

    const size_t WSTRIDE = (size_t)D_MODEL * D_MODEL;
    const float* Ws[4] = {Wq, Wk, Wv, Wo};

    conv_act_kernel<<<M_ROWS * D_MODEL / (256 * 4), 256>>>(x, ahi, alo);
    for (int w = 0; w < 4; w++)
        conv_wt_kernel<<<dim3(32, 32), dim3(32, 8)>>>(Ws[w], whi + w * WSTRIDE,
                                                      wlo + w * WSTRIDE);
    bias_kernel<<<(N_HEADS * S_LEN + 255) / 256, 256>>>(rel, bp);

    cudaFuncSetAttribute(hmma_gemm_kernel, cudaFuncAttributeMaxDynamicSharedMemorySize,
                         GEMM_SMEM);
    dim3 gg(D_MODEL / 128, M_ROWS / 128);
    hmma_gemm_kernel<<<gg, 256, GEMM_SMEM>>>(ahi, alo, whi + 0 * WSTRIDE,
                                             wlo + 0 * WSTRIDE, qp);
    hmma_gemm_kernel<<<gg, 256, GEMM_SMEM>>>(ahi, alo, whi + 1 * WSTRIDE,
                                             wlo + 1 * WSTRIDE, kp);
    hmma_gemm_kernel<<<gg, 256, GEMM_SMEM>>>(ahi, alo, whi + 2 * WSTRIDE,
                                             wlo + 2 * WSTRIDE, vp);

    rope_conv_kernel<<<M_ROWS, 512>>>(qp, kp, qhi, qlo, khi, klo);
    vt_conv_kernel<<<dim3(S_LEN / 32, HEAD_DIM / 32, BATCH * N_HEADS),
                     dim3(32, 8)>>>(vp, vthi, vtlo);

    cudaFuncSetAttribute(attn_kernel, cudaFuncAttributeMaxDynamicSharedMemorySize,
                         ATT_SMEM);
    attn_kernel<<<dim3(S_LEN / 64, BATCH * N_HEADS), 128, ATT_SMEM>>>(
        qhi, qlo, khi, klo, vthi, vtlo, bp, ahi, alo);

    hmma_gemm_kernel<<<gg, 256, GEMM_SMEM>>>(ahi, alo, whi + 3 * WSTRIDE,
                                             wlo + 3 * WSTRIDE, (float*)d_out);
}

// round 13
// speedup vs baseline: 3.5609x; 1.3656x over previous
#include <cuda_runtime.h>
#include <cuda_bf16.h>
#include <cuda_fp16.h>
#include <math.h>
#include <stdint.h>

#define S_LEN   2048
#define D_MODEL 1024
#define N_HEADS 16
#define HEAD_DIM 64
#define BATCH   2
#define M_ROWS  (BATCH * S_LEN)   // 4096

// ---------------- device scratch (no allocations allowed) ----------------
__device__ float g_q[M_ROWS * D_MODEL];
__device__ float g_k[M_ROWS * D_MODEL];
__device__ float g_v[M_ROWS * D_MODEL];
__device__ float g_bias[N_HEADS * S_LEN];
// fp16 GEMM operands
__device__ __half g_xh[M_ROWS * D_MODEL];               // activations / ctx (single plane)
__device__ __half g_whh[4][D_MODEL * D_MODEL];          // W^T hi  [N][K]
__device__ __half g_whl[4][D_MODEL * D_MODEL];          // W^T lo  [N][K]
// attention operands (bf16 hi/lo, proven path)
__device__ __nv_bfloat16 g_qhi[M_ROWS * D_MODEL];
__device__ __nv_bfloat16 g_qlo[M_ROWS * D_MODEL];
__device__ __nv_bfloat16 g_khi[M_ROWS * D_MODEL];
__device__ __nv_bfloat16 g_klo[M_ROWS * D_MODEL];
__device__ __nv_bfloat16 g_vthi[BATCH * N_HEADS * HEAD_DIM * S_LEN];
__device__ __nv_bfloat16 g_vtlo[BATCH * N_HEADS * HEAD_DIM * S_LEN];

// ---------------- mma.sync / ldmatrix / cp.async helpers ----------------
#define MMA_BF16(d, a, b) \
    asm volatile( \
        "mma.sync.aligned.m16n8k16.row.col.f32.bf16.bf16.f32 " \
        "{%0,%1,%2,%3}, {%4,%5,%6,%7}, {%8,%9}, {%0,%1,%2,%3};" \
        : "+f"((d)[0]), "+f"((d)[1]), "+f"((d)[2]), "+f"((d)[3]) \
        : "r"((a)[0]), "r"((a)[1]), "r"((a)[2]), "r"((a)[3]), \
          "r"((b)[0]), "r"((b)[1]))

#define MMA_F16(d, a, b) \
    asm volatile( \
        "mma.sync.aligned.m16n8k16.row.col.f32.f16.f16.f32 " \
        "{%0,%1,%2,%3}, {%4,%5,%6,%7}, {%8,%9}, {%0,%1,%2,%3};" \
        : "+f"((d)[0]), "+f"((d)[1]), "+f"((d)[2]), "+f"((d)[3]) \
        : "r"((a)[0]), "r"((a)[1]), "r"((a)[2]), "r"((a)[3]), \
          "r"((b)[0]), "r"((b)[1]))

#define LDSM_X4(r0, r1, r2, r3, addr) \
    asm volatile("ldmatrix.sync.aligned.m8n8.x4.shared.b16 {%0,%1,%2,%3}, [%4];" \
        : "=r"(r0), "=r"(r1), "=r"(r2), "=r"(r3) : "r"(addr))

__device__ __forceinline__ uint32_t smem_u32(const void* p) {
    uint32_t a;
    asm("{ .reg .u64 t; cvta.to.shared.u64 t, %1; cvt.u32.u64 %0, t; }" : "=r"(a) : "l"(p));
    return a;
}
__device__ __forceinline__ void cp_async16(uint32_t dst, const void* src) {
    asm volatile("cp.async.cg.shared.global [%0], [%1], 16;" :: "r"(dst), "l"(src));
}
#define CP_COMMIT() asm volatile("cp.async.commit_group;")
#define CP_WAIT(n)  asm volatile("cp.async.wait_group %0;" :: "n"(n))

// ---------------- conversion kernels ----------------
// x fp32 -> fp16 (single plane)
__global__ void conv_x_f16(const float* __restrict__ in, __half* __restrict__ out)
{
    size_t base = ((size_t)blockIdx.x * 256 + threadIdx.x) * 4;
    float4 v = *(const float4*)(in + base);
    __half2 p0 = __floats2half2_rn(v.x, v.y);
    __half2 p1 = __floats2half2_rn(v.z, v.w);
    uint2 pk = { *(uint32_t*)&p0, *(uint32_t*)&p1 };
    *(uint2*)(out + base) = pk;
}

// W [K,N] fp32 -> Wt [N,K] fp16 hi/lo
__global__ void conv_wt_f16(const float* __restrict__ W,
                            __half* __restrict__ hi, __half* __restrict__ lo)
{
    __shared__ float t[32][33];
    const int x0 = blockIdx.x * 32, y0 = blockIdx.y * 32;
    const int tx = threadIdx.x, ty = threadIdx.y;
#pragma unroll
    for (int j = 0; j < 4; j++) {
        int r = ty + j * 8;
        t[r][tx] = W[(size_t)(y0 + r) * D_MODEL + x0 + tx];
    }
    __syncthreads();
#pragma unroll
    for (int j = 0; j < 4; j++) {
        int r = ty + j * 8;
        float v = t[tx][r];
        __half h = __float2half_rn(v);
        size_t o = (size_t)(x0 + r) * D_MODEL + y0 + tx;
        hi[o] = h;
        lo[o] = __float2half_rn(v - __half2float(h));
    }
}

// ---------------- pipelined fp16 2-term HMMA GEMM ----------------
// C[4096,1024] = A @ W ; A fp16 [M,K]; W fp16 hi/lo [N,K].
// Tile 128x128, K-stage 64. Stage: A(16KB)+Bhi(16KB)+Blo(16KB)=48KB, 2 stages.
#define KSF 64
#define FTILE 16384                       // 128 rows x 128 B
#define FSTAGE (3 * FTILE)                // 49152
#define GEMM_SMEM (2 * FSTAGE)            // 98304

__device__ __forceinline__ void gemm_prefetch_f16(
    uint32_t stg, const __half* __restrict__ A,
    const __half* __restrict__ Bh, const __half* __restrict__ Bl,
    int gM, int gN, int k0, int tid)
{
#pragma unroll
    for (int it = 0; it < 4; it++) {
        int slot = it * 256 + tid;
        int r = slot >> 3, ch = slot & 7;
        uint32_t off = r * 128 + ((ch ^ (r & 7)) << 4);
        cp_async16(stg + off, A + (size_t)(gM + r) * D_MODEL + k0 + ch * 8);
        cp_async16(stg + FTILE + off, Bh + (size_t)(gN + r) * D_MODEL + k0 + ch * 8);
        cp_async16(stg + 2 * FTILE + off, Bl + (size_t)(gN + r) * D_MODEL + k0 + ch * 8);
    }
}

__global__ __launch_bounds__(256, 2) void hmma_gemm_f16(
    const __half* __restrict__ A,
    const __half* __restrict__ Bh, const __half* __restrict__ Bl,
    float* __restrict__ C)
{
    extern __shared__ char smem[];
    const uint32_t sbase = smem_u32(smem);
    const int tid = threadIdx.x;
    const int wid = tid >> 5, lane = tid & 31;
    const int g = lane >> 2, tg = lane & 3;
    const int mw = wid & 1, nw = wid >> 1;
    const int mBase = mw * 64, nBase = nw * 32;
    const int gM = blockIdx.y * 128, gN = blockIdx.x * 128;

    const int aRow = lane & 15;
    const int a_cb = lane >> 4;
    const int rB0 = ((lane >> 4) << 3) + (lane & 7);
    const int b_kpar = (lane >> 3) & 1;

    float d[4][4][4];
#pragma unroll
    for (int mt = 0; mt < 4; mt++)
#pragma unroll
        for (int nt = 0; nt < 4; nt++)
#pragma unroll
            for (int f = 0; f < 4; f++) d[mt][nt][f] = 0.0f;

    gemm_prefetch_f16(sbase, A, Bh, Bl, gM, gN, 0, tid);
    CP_COMMIT();

    const int NITER = D_MODEL / KSF;          // 16
    for (int itk = 0; itk < NITER; itk++) {
        if (itk + 1 < NITER) {
            gemm_prefetch_f16(sbase + ((itk + 1) & 1) * FSTAGE, A, Bh, Bl,
                              gM, gN, (itk + 1) * KSF, tid);
            CP_COMMIT();
            CP_WAIT(1);
        } else {
            CP_WAIT(0);
        }
        __syncthreads();

        const uint32_t stA = sbase + (itk & 1) * FSTAGE;
        const uint32_t stBh = stA + FTILE;
        const uint32_t stBl = stA + 2 * FTILE;

#pragma unroll
        for (int ks = 0; ks < 4; ks++) {
            const int chA = 2 * ks + a_cb;
            uint32_t a[4][4];
#pragma unroll
            for (int mt = 0; mt < 4; mt++) {
                int rA = mBase + mt * 16 + aRow;
                LDSM_X4(a[mt][0], a[mt][1], a[mt][2], a[mt][3],
                        stA + rA * 128 + ((chA ^ (rA & 7)) << 4));
            }
#pragma unroll
            for (int ntp = 0; ntp < 2; ntp++) {
                int rB = nBase + ntp * 16 + rB0;
                int chB = 2 * ks + b_kpar;
                uint32_t boff = rB * 128 + ((chB ^ (rB & 7)) << 4);
                uint32_t bh[4], bl[4];
                LDSM_X4(bh[0], bh[1], bh[2], bh[3], stBh + boff);
                LDSM_X4(bl[0], bl[1], bl[2], bl[3], stBl + boff);
#pragma unroll
                for (int mt = 0; mt < 4; mt++) {
                    MMA_F16(d[mt][2 * ntp], a[mt], bh);
                    MMA_F16(d[mt][2 * ntp], a[mt], bl);
                    MMA_F16(d[mt][2 * ntp + 1], a[mt], bh + 2);
                    MMA_F16(d[mt][2 * ntp + 1], a[mt], bl + 2);
                }
            }
        }
        __syncthreads();
    }

#pragma unroll
    for (int mt = 0; mt < 4; mt++) {
#pragma unroll
        for (int nt = 0; nt < 4; nt++) {
            int m = gM + mBase + mt * 16 + g;
            int n = gN + nBase + nt * 8 + tg * 2;
            float2 v0 = { d[mt][nt][0], d[mt][nt][1] };
            float2 v1 = { d[mt][nt][2], d[mt][nt][3] };
            *(float2*)(C + (size_t)m * D_MODEL + n) = v0;
            *(float2*)(C + (size_t)(m + 8) * D_MODEL + n) = v1;
        }
    }
}

// ---------------- RoPE + bf16 hi/lo split (fused) ----------------
__global__ void rope_conv_kernel(const float* __restrict__ q, const float* __restrict__ k,
                                 __nv_bfloat16* __restrict__ qhi, __nv_bfloat16* __restrict__ qlo,
                                 __nv_bfloat16* __restrict__ khi, __nv_bfloat16* __restrict__ klo)
{
    const int m = blockIdx.x;
    const int p = threadIdx.x;
    const int s = m & (S_LEN - 1);
    const int h = p >> 5, i = p & 31;

    float inv = exp2f(-((float)(2 * i) * (1.0f / 64.0f)) * 13.287712379549449f);
    float ang = (float)s * inv;
    float cs = cosf(ang), sn = sinf(ang);

    size_t i0 = (size_t)m * D_MODEL + h * HEAD_DIM + i;

    float a = q[i0], b = q[i0 + 32];
    float q0 = a * cs - b * sn;
    float q1 = b * cs + a * sn;
    a = k[i0]; b = k[i0 + 32];
    float k0 = a * cs - b * sn;
    float k1 = b * cs + a * sn;

    __nv_bfloat16 h0 = __float2bfloat16(q0), h1 = __float2bfloat16(q1);
    qhi[i0] = h0; qhi[i0 + 32] = h1;
    qlo[i0] = __float2bfloat16(q0 - __bfloat162float(h0));
    qlo[i0 + 32] = __float2bfloat16(q1 - __bfloat162float(h1));
    h0 = __float2bfloat16(k0); h1 = __float2bfloat16(k1);
    khi[i0] = h0; khi[i0 + 32] = h1;
    klo[i0] = __float2bfloat16(k0 - __bfloat162float(h0));
    klo[i0 + 32] = __float2bfloat16(k1 - __bfloat162float(h1));
}

// ---------------- V -> Vt[bh][hd][s] bf16 hi/lo ----------------
__global__ void vt_conv_kernel(const float* __restrict__ v,
                               __nv_bfloat16* __restrict__ vthi,
                               __nv_bfloat16* __restrict__ vtlo)
{
    __shared__ float t[32][33];
    const int s0 = blockIdx.x * 32, hd0 = blockIdx.y * 32, bh = blockIdx.z;
    const int b = bh >> 4, h = bh & 15;
    const int tx = threadIdx.x, ty = threadIdx.y;
#pragma unroll
    for (int j = 0; j < 4; j++) {
        int r = ty + j * 8;
        t[r][tx] = v[(size_t)(b * S_LEN + s0 + r) * D_MODEL + h * HEAD_DIM + hd0 + tx];
    }
    __syncthreads();
#pragma unroll
    for (int j = 0; j < 4; j++) {
        int r = ty + j * 8;
        float val = t[tx][r];
        __nv_bfloat16 hh = __float2bfloat16(val);
        size_t o = ((size_t)bh * HEAD_DIM + hd0 + r) * S_LEN + s0 + tx;
        vthi[o] = hh;
        vtlo[o] = __float2bfloat16(val - __bfloat162float(hh));
    }
}

// ---------------- relative-position bias table ----------------
__global__ void bias_kernel(const float* __restrict__ rel_emb, float* __restrict__ bias)
{
    int idx = blockIdx.x * 256 + threadIdx.x;
    if (idx >= N_HEADS * S_LEN) return;
    int h = idx / S_LEN;
    int d = idx % S_LEN;
    int bucket;
    if (d < 16) {
        bucket = d;
    } else {
        float v = logf((float)d * (1.0f / 16.0f)) / logf(8.0f) * 16.0f;
        bucket = 16 + (int)v;
        if (bucket > 31) bucket = 31;
    }
    bias[idx] = rel_emb[bucket * N_HEADS + h];
}

// ---------------- flash attention on HMMA (bf16 3-term; fp16 ctx out) -------
#define ASM_QHI 0
#define ASM_QLO 8192
#define ASM_KHI 16384
#define ASM_KLO 24576
#define ASM_VHI 32768
#define ASM_VLO 40960
#define ASM_BIAS 49152
#define ATT_SMEM (49152 + 512)

__device__ __forceinline__ void stage_tile(char* dst, const __nv_bfloat16* src,
                                           size_t rowStride, int tid) {
#pragma unroll
    for (int it = 0; it < 4; it++) {
        int slot = it * 128 + tid;
        int row = slot >> 3, ch = slot & 7;
        uint4 val = *(const uint4*)(src + (size_t)row * rowStride + ch * 8);
        *(uint4*)(dst + row * 128 + ((ch ^ (row & 7)) << 4)) = val;
    }
}

__global__ __launch_bounds__(128) void attn_kernel(
    const __nv_bfloat16* __restrict__ qhi_g, const __nv_bfloat16* __restrict__ qlo_g,
    const __nv_bfloat16* __restrict__ khi_g, const __nv_bfloat16* __restrict__ klo_g,
    const __nv_bfloat16* __restrict__ vthi_g, const __nv_bfloat16* __restrict__ vtlo_g,
    const float* __restrict__ bias, __half* __restrict__ ctx)
{
    extern __shared__ char smraw[];
    float* bias_s = (float*)(smraw + ASM_BIAS);
    const uint32_t sb = smem_u32(smraw);

    const int qb = (S_LEN / 64 - 1) - blockIdx.x;
    const int bh = blockIdx.y;
    const int b = bh >> 4, h = bh & 15;
    const int tid = threadIdx.x, wid = tid >> 5, lane = tid & 31;
    const int g = lane >> 2, tg = lane & 3;
    const int mBase = wid * 16;

    const int rowA = mBase + (lane & 15);
    const uint32_t offA_row = rowA * 128;
    const int a_r7 = rowA & 7;
    const int a_cb = lane >> 4;
    const int rB0 = ((lane >> 4) << 3) + (lane & 7);
    const int b_kpar = (lane >> 3) & 1;

    stage_tile(smraw + ASM_QHI,
               qhi_g + (size_t)(b * S_LEN + qb * 64) * D_MODEL + h * HEAD_DIM,
               D_MODEL, tid);
    stage_tile(smraw + ASM_QLO,
               qlo_g + (size_t)(b * S_LEN + qb * 64) * D_MODEL + h * HEAD_DIM,
               D_MODEL, tid);

    float o[8][4];
#pragma unroll
    for (int t = 0; t < 8; t++)
#pragma unroll
        for (int j = 0; j < 4; j++) o[t][j] = 0.0f;
    float m0 = -1e30f, m1 = -1e30f, l0 = 0.0f, l1 = 0.0f;

    for (int kt = 0; kt <= qb; kt++) {
        stage_tile(smraw + ASM_KHI,
                   khi_g + (size_t)(b * S_LEN + kt * 64) * D_MODEL + h * HEAD_DIM,
                   D_MODEL, tid);
        stage_tile(smraw + ASM_KLO,
                   klo_g + (size_t)(b * S_LEN + kt * 64) * D_MODEL + h * HEAD_DIM,
                   D_MODEL, tid);
        stage_tile(smraw + ASM_VHI,
                   vthi_g + (size_t)bh * HEAD_DIM * S_LEN + kt * 64, S_LEN, tid);
        stage_tile(smraw + ASM_VLO,
                   vtlo_g + (size_t)bh * HEAD_DIM * S_LEN + kt * 64, S_LEN, tid);
        {
            int dlt = (qb - kt) * 64 - 63 + tid;
            int dcl = dlt < 0 ? 0 : (dlt > S_LEN - 1 ? S_LEN - 1 : dlt);
            bias_s[tid] = bias[h * S_LEN + dcl];
        }
        __syncthreads();

        float c[8][4];
#pragma unroll
        for (int t = 0; t < 8; t++)
#pragma unroll
            for (int j = 0; j < 4; j++) c[t][j] = 0.0f;

#pragma unroll
        for (int ks = 0; ks < 4; ks++) {
            uint32_t aoff = offA_row + ((((ks * 2 + a_cb)) ^ a_r7) << 4);
            uint32_t qh[4], ql[4];
            LDSM_X4(qh[0], qh[1], qh[2], qh[3], sb + ASM_QHI + aoff);
            LDSM_X4(ql[0], ql[1], ql[2], ql[3], sb + ASM_QLO + aoff);
#pragma unroll
            for (int ntp = 0; ntp < 4; ntp++) {
                int rowB = ntp * 16 + rB0;
                uint32_t boff = rowB * 128 + (((ks * 2 + b_kpar) ^ (rowB & 7)) << 4);
                uint32_t kh[4], kl[4];
                LDSM_X4(kh[0], kh[1], kh[2], kh[3], sb + ASM_KHI + boff);
                LDSM_X4(kl[0], kl[1], kl[2], kl[3], sb + ASM_KLO + boff);
                MMA_BF16(c[2 * ntp], qh, kh);
                MMA_BF16(c[2 * ntp], qh, kl);
                MMA_BF16(c[2 * ntp], ql, kh);
                MMA_BF16(c[2 * ntp + 1], qh, kh + 2);
                MMA_BF16(c[2 * ntp + 1], qh, kl + 2);
                MMA_BF16(c[2 * ntp + 1], ql, kh + 2);
            }
        }

        const bool diag = (kt == qb);
        const int rr0 = mBase + g, rr1 = rr0 + 8;
        float mx0 = -1e30f, mx1 = -1e30f;
#pragma unroll
        for (int t = 0; t < 8; t++) {
            int cbase = t * 8 + 2 * tg;
            float s0 = c[t][0] * 0.125f + bias_s[rr0 - cbase + 63];
            float s1 = c[t][1] * 0.125f + bias_s[rr0 - cbase + 62];
            float s2 = c[t][2] * 0.125f + bias_s[rr1 - cbase + 63];
            float s3 = c[t][3] * 0.125f + bias_s[rr1 - cbase + 62];
            if (diag) {
                if (cbase     > rr0) s0 = -1e9f;
                if (cbase + 1 > rr0) s1 = -1e9f;
                if (cbase     > rr1) s2 = -1e9f;
                if (cbase + 1 > rr1) s3 = -1e9f;
            }
            c[t][0] = s0; c[t][1] = s1; c[t][2] = s2; c[t][3] = s3;
            mx0 = fmaxf(mx0, fmaxf(s0, s1));
            mx1 = fmaxf(mx1, fmaxf(s2, s3));
        }
        mx0 = fmaxf(mx0, __shfl_xor_sync(0xffffffffu, mx0, 1));
        mx0 = fmaxf(mx0, __shfl_xor_sync(0xffffffffu, mx0, 2));
        mx1 = fmaxf(mx1, __shfl_xor_sync(0xffffffffu, mx1, 1));
        mx1 = fmaxf(mx1, __shfl_xor_sync(0xffffffffu, mx1, 2));
        float m0n = fmaxf(m0, mx0), m1n = fmaxf(m1, mx1);
        float corr0 = __expf(m0 - m0n), corr1 = __expf(m1 - m1n);
        m0 = m0n; m1 = m1n;

        float s0sum = 0.0f, s1sum = 0.0f;
        uint32_t phiA[8], ploA[8], phiB[8], ploB[8];
#pragma unroll
        for (int t = 0; t < 8; t++) {
            float p0 = __expf(c[t][0] - m0n), p1 = __expf(c[t][1] - m0n);
            float p2 = __expf(c[t][2] - m1n), p3 = __expf(c[t][3] - m1n);
            s0sum += p0 + p1; s1sum += p2 + p3;
            __nv_bfloat16 h0 = __float2bfloat16(p0), h1 = __float2bfloat16(p1);
            phiA[t] = ((uint32_t)__bfloat16_as_ushort(h1) << 16) | __bfloat16_as_ushort(h0);
            __nv_bfloat16 e0 = __float2bfloat16(p0 - __bfloat162float(h0));
            __nv_bfloat16 e1 = __float2bfloat16(p1 - __bfloat162float(h1));
            ploA[t] = ((uint32_t)__bfloat16_as_ushort(e1) << 16) | __bfloat16_as_ushort(e0);
            h0 = __float2bfloat16(p2); h1 = __float2bfloat16(p3);
            phiB[t] = ((uint32_t)__bfloat16_as_ushort(h1) << 16) | __bfloat16_as_ushort(h0);
            e0 = __float2bfloat16(p2 - __bfloat162float(h0));
            e1 = __float2bfloat16(p3 - __bfloat162float(h1));
            ploB[t] = ((uint32_t)__bfloat16_as_ushort(e1) << 16) | __bfloat16_as_ushort(e0);
        }
        s0sum += __shfl_xor_sync(0xffffffffu, s0sum, 1);
        s0sum += __shfl_xor_sync(0xffffffffu, s0sum, 2);
        s1sum += __shfl_xor_sync(0xffffffffu, s1sum, 1);
        s1sum += __shfl_xor_sync(0xffffffffu, s1sum, 2);
        l0 = l0 * corr0 + s0sum;
        l1 = l1 * corr1 + s1sum;
#pragma unroll
        for (int t = 0; t < 8; t++) {
            o[t][0] *= corr0; o[t][1] *= corr0;
            o[t][2] *= corr1; o[t][3] *= corr1;
        }

#pragma unroll
        for (int kt2 = 0; kt2 < 4; kt2++) {
            uint32_t pah[4] = { phiA[2 * kt2], phiB[2 * kt2],
                                phiA[2 * kt2 + 1], phiB[2 * kt2 + 1] };
            uint32_t pal[4] = { ploA[2 * kt2], ploB[2 * kt2],
                                ploA[2 * kt2 + 1], ploB[2 * kt2 + 1] };
#pragma unroll
            for (int ntp = 0; ntp < 4; ntp++) {
                int rowB = ntp * 16 + rB0;
                uint32_t boff = rowB * 128 + (((kt2 * 2 + b_kpar) ^ (rowB & 7)) << 4);
                uint32_t vh[4], vl[4];
                LDSM_X4(vh[0], vh[1], vh[2], vh[3], sb + ASM_VHI + boff);
                LDSM_X4(vl[0], vl[1], vl[2], vl[3], sb + ASM_VLO + boff);
                MMA_BF16(o[2 * ntp], pah, vh);
                MMA_BF16(o[2 * ntp], pah, vl);
                MMA_BF16(o[2 * ntp], pal, vh);
                MMA_BF16(o[2 * ntp + 1], pah, vh + 2);
                MMA_BF16(o[2 * ntp + 1], pah, vl + 2);
                MMA_BF16(o[2 * ntp + 1], pal, vh + 2);
            }
        }
        __syncthreads();
    }

    // ---- epilogue: normalize, emit fp16 ctx directly ----
    float inv0 = 1.0f / l0, inv1 = 1.0f / l1;
    const int row0 = b * S_LEN + qb * 64 + mBase + g;
    const int row1 = row0 + 8;
#pragma unroll
    for (int t = 0; t < 8; t++) {
        int col = h * HEAD_DIM + t * 8 + 2 * tg;
        __half2 p0 = __floats2half2_rn(o[t][0] * inv0, o[t][1] * inv0);
        __half2 p1 = __floats2half2_rn(o[t][2] * inv1, o[t][3] * inv1);
        *(__half2*)(ctx + (size_t)row0 * D_MODEL + col) = p0;
        *(__half2*)(ctx + (size_t)row1 * D_MODEL + col) = p1;
    }
}

// ---------------- launcher ----------------
extern "C" void kernel_launch(void* const* d_in, const int* in_sizes, int n_in,
                              void* d_out, int out_size)
{
    const float* x   = (const float*)d_in[0];
    const float* Wq  = (const float*)d_in[1];
    const float* Wk  = (const float*)d_in[2];
    const float* Wv  = (const float*)d_in[3];
    const float* Wo  = (const float*)d_in[4];
    const float* rel = (const float*)d_in[5];

    float *qp, *kp, *vp, *bp;
    __half *xh, *whh, *whl;
    __nv_bfloat16 *qhi, *qlo, *khi, *klo, *vthi, *vtlo;
    cudaGetSymbolAddress((void**)&qp, g_q);
    cudaGetSymbolAddress((void**)&kp, g_k);
    cudaGetSymbolAddress((void**)&vp, g_v);
    cudaGetSymbolAddress((void**)&bp, g_bias);
    cudaGetSymbolAddress((void**)&xh, g_xh);
    cudaGetSymbolAddress((void**)&whh, g_whh);
    cudaGetSymbolAddress((void**)&whl, g_whl);
    cudaGetSymbolAddress((void**)&qhi, g_qhi);
    cudaGetSymbolAddress((void**)&qlo, g_qlo);
    cudaGetSymbolAddress((void**)&khi, g_khi);
    cudaGetSymbolAddress((void**)&klo, g_klo);
    cudaGetSymbolAddress((void**)&vthi, g_vthi);
    cudaGetSymbolAddress((void**)&vtlo, g_vtlo);

    const size_t WSTRIDE = (size_t)D_MODEL * D_MODEL;
    const float* Ws[4] = {Wq, Wk, Wv, Wo};

    conv_x_f16<<<M_ROWS * D_MODEL / (256 * 4), 256>>>(x, xh);
    for (int w = 0; w < 4; w++)
        conv_wt_f16<<<dim3(32, 32), dim3(32, 8)>>>(Ws[w], whh + w * WSTRIDE,
                                                   whl + w * WSTRIDE);
    bias_kernel<<<(N_HEADS * S_LEN + 255) / 256, 256>>>(rel, bp);

    cudaFuncSetAttribute(hmma_gemm_f16, cudaFuncAttributeMaxDynamicSharedMemorySize,
                         GEMM_SMEM);
    dim3 gg(D_MODEL / 128, M_ROWS / 128);
    hmma_gemm_f16<<<gg, 256, GEMM_SMEM>>>(xh, whh + 0 * WSTRIDE, whl + 0 * WSTRIDE, qp);
    hmma_gemm_f16<<<gg, 256, GEMM_SMEM>>>(xh, whh + 1 * WSTRIDE, whl + 1 * WSTRIDE, kp);
    hmma_gemm_f16<<<gg, 256, GEMM_SMEM>>>(xh, whh + 2 * WSTRIDE, whl + 2 * WSTRIDE, vp);

    rope_conv_kernel<<<M_ROWS, 512>>>(qp, kp, qhi, qlo, khi, klo);
    vt_conv_kernel<<<dim3(S_LEN / 32, HEAD_DIM / 32, BATCH * N_HEADS),
                     dim3(32, 8)>>>(vp, vthi, vtlo);

    cudaFuncSetAttribute(attn_kernel, cudaFuncAttributeMaxDynamicSharedMemorySize,
                         ATT_SMEM);
    attn_kernel<<<dim3(S_LEN / 64, BATCH * N_HEADS), 128, ATT_SMEM>>>(
        qhi, qlo, khi, klo, vthi, vtlo, bp, xh);

    hmma_gemm_f16<<<gg, 256, GEMM_SMEM>>>(xh, whh + 3 * WSTRIDE, whl + 3 * WSTRIDE,
                                          (float*)d_out);
}

// round 16
// speedup vs baseline: 3.6396x; 1.0221x over previous
#include <cuda_runtime.h>
#include <cuda_bf16.h>
#include <cuda_fp16.h>
#include <math.h>
#include <stdint.h>

#define S_LEN   2048
#define D_MODEL 1024
#define N_HEADS 16
#define HEAD_DIM 64
#define BATCH   2
#define M_ROWS  (BATCH * S_LEN)   // 4096

// ---------------- device scratch (no allocations allowed) ----------------
__device__ float g_q[M_ROWS * D_MODEL];
__device__ float g_k[M_ROWS * D_MODEL];
__device__ float g_v[M_ROWS * D_MODEL];
__device__ float g_bias[N_HEADS * S_LEN];
__device__ __half g_xh[M_ROWS * D_MODEL];               // activations / ctx (fp16)
__device__ __half g_whh[4][D_MODEL * D_MODEL];          // W^T hi  [N][K]
__device__ __half g_whl[4][D_MODEL * D_MODEL];          // W^T lo  [N][K]
__device__ __nv_bfloat16 g_qhi[M_ROWS * D_MODEL];
__device__ __nv_bfloat16 g_qlo[M_ROWS * D_MODEL];
__device__ __nv_bfloat16 g_khi[M_ROWS * D_MODEL];
__device__ __nv_bfloat16 g_klo[M_ROWS * D_MODEL];
__device__ __nv_bfloat16 g_vthi[BATCH * N_HEADS * HEAD_DIM * S_LEN];
__device__ __nv_bfloat16 g_vtlo[BATCH * N_HEADS * HEAD_DIM * S_LEN];

// ---------------- mma.sync / ldmatrix / cp.async helpers ----------------
#define MMA_BF16(d, a, b) \
    asm volatile( \
        "mma.sync.aligned.m16n8k16.row.col.f32.bf16.bf16.f32 " \
        "{%0,%1,%2,%3}, {%4,%5,%6,%7}, {%8,%9}, {%0,%1,%2,%3};" \
        : "+f"((d)[0]), "+f"((d)[1]), "+f"((d)[2]), "+f"((d)[3]) \
        : "r"((a)[0]), "r"((a)[1]), "r"((a)[2]), "r"((a)[3]), \
          "r"((b)[0]), "r"((b)[1]))

#define MMA_F16(d, a, b) \
    asm volatile( \
        "mma.sync.aligned.m16n8k16.row.col.f32.f16.f16.f32 " \
        "{%0,%1,%2,%3}, {%4,%5,%6,%7}, {%8,%9}, {%0,%1,%2,%3};" \
        : "+f"((d)[0]), "+f"((d)[1]), "+f"((d)[2]), "+f"((d)[3]) \
        : "r"((a)[0]), "r"((a)[1]), "r"((a)[2]), "r"((a)[3]), \
          "r"((b)[0]), "r"((b)[1]))

#define LDSM_X4(r0, r1, r2, r3, addr) \
    asm volatile("ldmatrix.sync.aligned.m8n8.x4.shared.b16 {%0,%1,%2,%3}, [%4];" \
        : "=r"(r0), "=r"(r1), "=r"(r2), "=r"(r3) : "r"(addr))

__device__ __forceinline__ uint32_t smem_u32(const void* p) {
    uint32_t a;
    asm("{ .reg .u64 t; cvta.to.shared.u64 t, %1; cvt.u32.u64 %0, t; }" : "=r"(a) : "l"(p));
    return a;
}
__device__ __forceinline__ void cp_async16(uint32_t dst, const void* src) {
    asm volatile("cp.async.cg.shared.global [%0], [%1], 16;" :: "r"(dst), "l"(src));
}
#define CP_COMMIT() asm volatile("cp.async.commit_group;")
#define CP_WAIT(n)  asm volatile("cp.async.wait_group %0;" :: "n"(n))

// ---------------- conversion kernels ----------------
__global__ void conv_x_f16(const float* __restrict__ in, __half* __restrict__ out)
{
    size_t base = ((size_t)blockIdx.x * 256 + threadIdx.x) * 4;
    float4 v = *(const float4*)(in + base);
    __half2 p0 = __floats2half2_rn(v.x, v.y);
    __half2 p1 = __floats2half2_rn(v.z, v.w);
    uint2 pk = { *(uint32_t*)&p0, *(uint32_t*)&p1 };
    *(uint2*)(out + base) = pk;
}

// W [K,N] fp32 -> Wt [N,K] fp16 hi/lo ; all four weights in one launch (z)
__global__ void conv_wt_f16(const float* __restrict__ W0, const float* __restrict__ W1,
                            const float* __restrict__ W2, const float* __restrict__ W3,
                            __half* __restrict__ hi_base, __half* __restrict__ lo_base)
{
    const int z = blockIdx.z;
    const float* W = (z == 0) ? W0 : (z == 1) ? W1 : (z == 2) ? W2 : W3;
    __half* hi = hi_base + (size_t)z * D_MODEL * D_MODEL;
    __half* lo = lo_base + (size_t)z * D_MODEL * D_MODEL;

    __shared__ float t[32][33];
    const int x0 = blockIdx.x * 32, y0 = blockIdx.y * 32;
    const int tx = threadIdx.x, ty = threadIdx.y;
#pragma unroll
    for (int j = 0; j < 4; j++) {
        int r = ty + j * 8;
        t[r][tx] = W[(size_t)(y0 + r) * D_MODEL + x0 + tx];
    }
    __syncthreads();
#pragma unroll
    for (int j = 0; j < 4; j++) {
        int r = ty + j * 8;
        float v = t[tx][r];
        __half h = __float2half_rn(v);
        size_t o = (size_t)(x0 + r) * D_MODEL + y0 + tx;
        hi[o] = h;
        lo[o] = __float2half_rn(v - __half2float(h));
    }
}

// ---------------- fp16 2-term HMMA GEMM, attention-shaped ----------------
// Tile 64x64, 128 threads (4 warps), warp = 16 rows x 64 cols, c[8][4].
// 2-stage cp.async, K-stage 64. Stage = A(8KB)+Bh(8KB)+Bl(8KB) = 24KB.
#define G2_ATILE 8192
#define G2_STAGE (3 * G2_ATILE)           // 24576
#define G2_SMEM (2 * G2_STAGE)            // 49152

__device__ __forceinline__ void g2_prefetch(
    uint32_t stg, const __half* __restrict__ A,
    const __half* __restrict__ Bh, const __half* __restrict__ Bl,
    int gM, int gN, int k0, int tid)
{
#pragma unroll
    for (int it = 0; it < 4; it++) {
        int slot = it * 128 + tid;            // 0..511
        int r = slot >> 3, ch = slot & 7;
        uint32_t off = r * 128 + ((ch ^ (r & 7)) << 4);
        cp_async16(stg + off, A + (size_t)(gM + r) * D_MODEL + k0 + ch * 8);
        cp_async16(stg + G2_ATILE + off, Bh + (size_t)(gN + r) * D_MODEL + k0 + ch * 8);
        cp_async16(stg + 2 * G2_ATILE + off, Bl + (size_t)(gN + r) * D_MODEL + k0 + ch * 8);
    }
}

__global__ __launch_bounds__(128, 4) void hmma_gemm64(
    const __half* __restrict__ A,
    const __half* __restrict__ Wh_base, const __half* __restrict__ Wl_base,
    float* __restrict__ C0, float* __restrict__ C1, float* __restrict__ C2)
{
    extern __shared__ char smem[];
    const uint32_t sbase = smem_u32(smem);
    const int z = blockIdx.z;
    const __half* Bh = Wh_base + (size_t)z * D_MODEL * D_MODEL;
    const __half* Bl = Wl_base + (size_t)z * D_MODEL * D_MODEL;
    float* C = (z == 0) ? C0 : (z == 1) ? C1 : C2;

    const int gM = blockIdx.x * 64, gN = blockIdx.y * 64;
    const int tid = threadIdx.x, wid = tid >> 5, lane = tid & 31;
    const int g = lane >> 2, tg = lane & 3;
    const int mBase = wid * 16;

    // ldmatrix lane addressing (identical to attention kernel)
    const int rowA = mBase + (lane & 15);
    const int a_r7 = rowA & 7;
    const int a_cb = lane >> 4;
    const int rB0 = ((lane >> 4) << 3) + (lane & 7);
    const int b_kpar = (lane >> 3) & 1;

    float c[8][4];
#pragma unroll
    for (int t = 0; t < 8; t++)
#pragma unroll
        for (int j = 0; j < 4; j++) c[t][j] = 0.0f;

    g2_prefetch(sbase, A, Bh, Bl, gM, gN, 0, tid);
    CP_COMMIT();

    const int NITER = D_MODEL / 64;           // 16
    for (int itk = 0; itk < NITER; itk++) {
        if (itk + 1 < NITER) {
            g2_prefetch(sbase + ((itk + 1) & 1) * G2_STAGE, A, Bh, Bl,
                        gM, gN, (itk + 1) * 64, tid);
            CP_COMMIT();
            CP_WAIT(1);
        } else {
            CP_WAIT(0);
        }
        __syncthreads();

        const uint32_t stA = sbase + (itk & 1) * G2_STAGE;
        const uint32_t stBh = stA + G2_ATILE;
        const uint32_t stBl = stA + 2 * G2_ATILE;

#pragma unroll
        for (int ks = 0; ks < 4; ks++) {
            uint32_t a[4];
            LDSM_X4(a[0], a[1], a[2], a[3],
                    stA + rowA * 128 + (((2 * ks + a_cb) ^ a_r7) << 4));
            uint32_t bh[16], bl[16];
#pragma unroll
            for (int ntp = 0; ntp < 4; ntp++) {
                int rowB = ntp * 16 + rB0;
                uint32_t boff = rowB * 128 + (((2 * ks + b_kpar) ^ (rowB & 7)) << 4);
                LDSM_X4(bh[4 * ntp], bh[4 * ntp + 1], bh[4 * ntp + 2], bh[4 * ntp + 3],
                        stBh + boff);
                LDSM_X4(bl[4 * ntp], bl[4 * ntp + 1], bl[4 * ntp + 2], bl[4 * ntp + 3],
                        stBl + boff);
            }
            // 8 independent hi-term MMAs, then 8 lo-term (reuse distance 8)
#pragma unroll
            for (int t = 0; t < 8; t++) MMA_F16(c[t], a, &bh[2 * t]);
#pragma unroll
            for (int t = 0; t < 8; t++) MMA_F16(c[t], a, &bl[2 * t]);
        }
        __syncthreads();
    }

    // epilogue (fragment->element mapping as attention kernel)
    const int row0 = gM + mBase + g;
#pragma unroll
    for (int t = 0; t < 8; t++) {
        int n = gN + t * 8 + 2 * tg;
        float2 v0 = { c[t][0], c[t][1] };
        float2 v1 = { c[t][2], c[t][3] };
        *(float2*)(C + (size_t)row0 * D_MODEL + n) = v0;
        *(float2*)(C + (size_t)(row0 + 8) * D_MODEL + n) = v1;
    }
}

// ---------------- RoPE + bf16 hi/lo split (fused) ----------------
__global__ void rope_conv_kernel(const float* __restrict__ q, const float* __restrict__ k,
                                 __nv_bfloat16* __restrict__ qhi, __nv_bfloat16* __restrict__ qlo,
                                 __nv_bfloat16* __restrict__ khi, __nv_bfloat16* __restrict__ klo)
{
    const int m = blockIdx.x;
    const int p = threadIdx.x;
    const int s = m & (S_LEN - 1);
    const int h = p >> 5, i = p & 31;

    float inv = exp2f(-((float)(2 * i) * (1.0f / 64.0f)) * 13.287712379549449f);
    float ang = (float)s * inv;
    float cs = cosf(ang), sn = sinf(ang);

    size_t i0 = (size_t)m * D_MODEL + h * HEAD_DIM + i;

    float a = q[i0], b = q[i0 + 32];
    float q0 = a * cs - b * sn;
    float q1 = b * cs + a * sn;
    a = k[i0]; b = k[i0 + 32];
    float k0 = a * cs - b * sn;
    float k1 = b * cs + a * sn;

    __nv_bfloat16 h0 = __float2bfloat16(q0), h1 = __float2bfloat16(q1);
    qhi[i0] = h0; qhi[i0 + 32] = h1;
    qlo[i0] = __float2bfloat16(q0 - __bfloat162float(h0));
    qlo[i0 + 32] = __float2bfloat16(q1 - __bfloat162float(h1));
    h0 = __float2bfloat16(k0); h1 = __float2bfloat16(k1);
    khi[i0] = h0; khi[i0 + 32] = h1;
    klo[i0] = __float2bfloat16(k0 - __bfloat162float(h0));
    klo[i0 + 32] = __float2bfloat16(k1 - __bfloat162float(h1));
}

// ---------------- V -> Vt[bh][hd][s] bf16 hi/lo ----------------
__global__ void vt_conv_kernel(const float* __restrict__ v,
                               __nv_bfloat16* __restrict__ vthi,
                               __nv_bfloat16* __restrict__ vtlo)
{
    __shared__ float t[32][33];
    const int s0 = blockIdx.x * 32, hd0 = blockIdx.y * 32, bh = blockIdx.z;
    const int b = bh >> 4, h = bh & 15;
    const int tx = threadIdx.x, ty = threadIdx.y;
#pragma unroll
    for (int j = 0; j < 4; j++) {
        int r = ty + j * 8;
        t[r][tx] = v[(size_t)(b * S_LEN + s0 + r) * D_MODEL + h * HEAD_DIM + hd0 + tx];
    }
    __syncthreads();
#pragma unroll
    for (int j = 0; j < 4; j++) {
        int r = ty + j * 8;
        float val = t[tx][r];
        __nv_bfloat16 hh = __float2bfloat16(val);
        size_t o = ((size_t)bh * HEAD_DIM + hd0 + r) * S_LEN + s0 + tx;
        vthi[o] = hh;
        vtlo[o] = __float2bfloat16(val - __bfloat162float(hh));
    }
}

// ---------------- relative-position bias table ----------------
__global__ void bias_kernel(const float* __restrict__ rel_emb, float* __restrict__ bias)
{
    int idx = blockIdx.x * 256 + threadIdx.x;
    if (idx >= N_HEADS * S_LEN) return;
    int h = idx / S_LEN;
    int d = idx % S_LEN;
    int bucket;
    if (d < 16) {
        bucket = d;
    } else {
        float v = logf((float)d * (1.0f / 16.0f)) / logf(8.0f) * 16.0f;
        bucket = 16 + (int)v;
        if (bucket > 31) bucket = 31;
    }
    bias[idx] = rel_emb[bucket * N_HEADS + h];
}

// ---------------- flash attention on HMMA (bf16 3-term; fp16 ctx out) -------
#define ASM_QHI 0
#define ASM_QLO 8192
#define ASM_KHI 16384
#define ASM_KLO 24576
#define ASM_VHI 32768
#define ASM_VLO 40960
#define ASM_BIAS 49152
#define ATT_SMEM (49152 + 512)

__device__ __forceinline__ void stage_tile(char* dst, const __nv_bfloat16* src,
                                           size_t rowStride, int tid) {
#pragma unroll
    for (int it = 0; it < 4; it++) {
        int slot = it * 128 + tid;
        int row = slot >> 3, ch = slot & 7;
        uint4 val = *(const uint4*)(src + (size_t)row * rowStride + ch * 8);
        *(uint4*)(dst + row * 128 + ((ch ^ (row & 7)) << 4)) = val;
    }
}

__global__ __launch_bounds__(128) void attn_kernel(
    const __nv_bfloat16* __restrict__ qhi_g, const __nv_bfloat16* __restrict__ qlo_g,
    const __nv_bfloat16* __restrict__ khi_g, const __nv_bfloat16* __restrict__ klo_g,
    const __nv_bfloat16* __restrict__ vthi_g, const __nv_bfloat16* __restrict__ vtlo_g,
    const float* __restrict__ bias, __half* __restrict__ ctx)
{
    extern __shared__ char smraw[];
    float* bias_s = (float*)(smraw + ASM_BIAS);
    const uint32_t sb = smem_u32(smraw);

    const int qb = (S_LEN / 64 - 1) - blockIdx.x;
    const int bh = blockIdx.y;
    const int b = bh >> 4, h = bh & 15;
    const int tid = threadIdx.x, wid = tid >> 5, lane = tid & 31;
    const int g = lane >> 2, tg = lane & 3;
    const int mBase = wid * 16;

    const int rowA = mBase + (lane & 15);
    const uint32_t offA_row = rowA * 128;
    const int a_r7 = rowA & 7;
    const int a_cb = lane >> 4;
    const int rB0 = ((lane >> 4) << 3) + (lane & 7);
    const int b_kpar = (lane >> 3) & 1;

    stage_tile(smraw + ASM_QHI,
               qhi_g + (size_t)(b * S_LEN + qb * 64) * D_MODEL + h * HEAD_DIM,
               D_MODEL, tid);
    stage_tile(smraw + ASM_QLO,
               qlo_g + (size_t)(b * S_LEN + qb * 64) * D_MODEL + h * HEAD_DIM,
               D_MODEL, tid);

    float o[8][4];
#pragma unroll
    for (int t = 0; t < 8; t++)
#pragma unroll
        for (int j = 0; j < 4; j++) o[t][j] = 0.0f;
    float m0 = -1e30f, m1 = -1e30f, l0 = 0.0f, l1 = 0.0f;

    for (int kt = 0; kt <= qb; kt++) {
        stage_tile(smraw + ASM_KHI,
                   khi_g + (size_t)(b * S_LEN + kt * 64) * D_MODEL + h * HEAD_DIM,
                   D_MODEL, tid);
        stage_tile(smraw + ASM_KLO,
                   klo_g + (size_t)(b * S_LEN + kt * 64) * D_MODEL + h * HEAD_DIM,
                   D_MODEL, tid);
        stage_tile(smraw + ASM_VHI,
                   vthi_g + (size_t)bh * HEAD_DIM * S_LEN + kt * 64, S_LEN, tid);
        stage_tile(smraw + ASM_VLO,
                   vtlo_g + (size_t)bh * HEAD_DIM * S_LEN + kt * 64, S_LEN, tid);
        {
            int dlt = (qb - kt) * 64 - 63 + tid;
            int dcl = dlt < 0 ? 0 : (dlt > S_LEN - 1 ? S_LEN - 1 : dlt);
            bias_s[tid] = bias[h * S_LEN + dcl];
        }
        __syncthreads();

        float c[8][4];
#pragma unroll
        for (int t = 0; t < 8; t++)
#pragma unroll
            for (int j = 0; j < 4; j++) c[t][j] = 0.0f;

#pragma unroll
        for (int ks = 0; ks < 4; ks++) {
            uint32_t aoff = offA_row + ((((ks * 2 + a_cb)) ^ a_r7) << 4);
            uint32_t qh[4], ql[4];
            LDSM_X4(qh[0], qh[1], qh[2], qh[3], sb + ASM_QHI + aoff);
            LDSM_X4(ql[0], ql[1], ql[2], ql[3], sb + ASM_QLO + aoff);
#pragma unroll
            for (int ntp = 0; ntp < 4; ntp++) {
                int rowB = ntp * 16 + rB0;
                uint32_t boff = rowB * 128 + (((ks * 2 + b_kpar) ^ (rowB & 7)) << 4);
                uint32_t kh[4], kl[4];
                LDSM_X4(kh[0], kh[1], kh[2], kh[3], sb + ASM_KHI + boff);
                LDSM_X4(kl[0], kl[1], kl[2], kl[3], sb + ASM_KLO + boff);
                MMA_BF16(c[2 * ntp], qh, kh);
                MMA_BF16(c[2 * ntp], qh, kl);
                MMA_BF16(c[2 * ntp], ql, kh);
                MMA_BF16(c[2 * ntp + 1], qh, kh + 2);
                MMA_BF16(c[2 * ntp + 1], qh, kl + 2);
                MMA_BF16(c[2 * ntp + 1], ql, kh + 2);
            }
        }

        const bool diag = (kt == qb);
        const int rr0 = mBase + g, rr1 = rr0 + 8;
        float mx0 = -1e30f, mx1 = -1e30f;
#pragma unroll
        for (int t = 0; t < 8; t++) {
            int cbase = t * 8 + 2 * tg;
            float s0 = c[t][0] * 0.125f + bias_s[rr0 - cbase + 63];
            float s1 = c[t][1] * 0.125f + bias_s[rr0 - cbase + 62];
            float s2 = c[t][2] * 0.125f + bias_s[rr1 - cbase + 63];
            float s3 = c[t][3] * 0.125f + bias_s[rr1 - cbase + 62];
            if (diag) {
                if (cbase     > rr0) s0 = -1e9f;
                if (cbase + 1 > rr0) s1 = -1e9f;
                if (cbase     > rr1) s2 = -1e9f;
                if (cbase + 1 > rr1) s3 = -1e9f;
            }
            c[t][0] = s0; c[t][1] = s1; c[t][2] = s2; c[t][3] = s3;
            mx0 = fmaxf(mx0, fmaxf(s0, s1));
            mx1 = fmaxf(mx1, fmaxf(s2, s3));
        }
        mx0 = fmaxf(mx0, __shfl_xor_sync(0xffffffffu, mx0, 1));
        mx0 = fmaxf(mx0, __shfl_xor_sync(0xffffffffu, mx0, 2));
        mx1 = fmaxf(mx1, __shfl_xor_sync(0xffffffffu, mx1, 1));
        mx1 = fmaxf(mx1, __shfl_xor_sync(0xffffffffu, mx1, 2));
        float m0n = fmaxf(m0, mx0), m1n = fmaxf(m1, mx1);
        float corr0 = __expf(m0 - m0n), corr1 = __expf(m1 - m1n);
        m0 = m0n; m1 = m1n;

        float s0sum = 0.0f, s1sum = 0.0f;
        uint32_t phiA[8], ploA[8], phiB[8], ploB[8];
#pragma unroll
        for (int t = 0; t < 8; t++) {
            float p0 = __expf(c[t][0] - m0n), p1 = __expf(c[t][1] - m0n);
            float p2 = __expf(c[t][2] - m1n), p3 = __expf(c[t][3] - m1n);
            s0sum += p0 + p1; s1sum += p2 + p3;
            __nv_bfloat16 h0 = __float2bfloat16(p0), h1 = __float2bfloat16(p1);
            phiA[t] = ((uint32_t)__bfloat16_as_ushort(h1) << 16) | __bfloat16_as_ushort(h0);
            __nv_bfloat16 e0 = __float2bfloat16(p0 - __bfloat162float(h0));
            __nv_bfloat16 e1 = __float2bfloat16(p1 - __bfloat162float(h1));
            ploA[t] = ((uint32_t)__bfloat16_as_ushort(e1) << 16) | __bfloat16_as_ushort(e0);
            h0 = __float2bfloat16(p2); h1 = __float2bfloat16(p3);
            phiB[t] = ((uint32_t)__bfloat16_as_ushort(h1) << 16) | __bfloat16_as_ushort(h0);
            e0 = __float2bfloat16(p2 - __bfloat162float(h0));
            e1 = __float2bfloat16(p3 - __bfloat162float(h1));
            ploB[t] = ((uint32_t)__bfloat16_as_ushort(e1) << 16) | __bfloat16_as_ushort(e0);
        }
        s0sum += __shfl_xor_sync(0xffffffffu, s0sum, 1);
        s0sum += __shfl_xor_sync(0xffffffffu, s0sum, 2);
        s1sum += __shfl_xor_sync(0xffffffffu, s1sum, 1);
        s1sum += __shfl_xor_sync(0xffffffffu, s1sum, 2);
        l0 = l0 * corr0 + s0sum;
        l1 = l1 * corr1 + s1sum;
#pragma unroll
        for (int t = 0; t < 8; t++) {
            o[t][0] *= corr0; o[t][1] *= corr0;
            o[t][2] *= corr1; o[t][3] *= corr1;
        }

#pragma unroll
        for (int kt2 = 0; kt2 < 4; kt2++) {
            uint32_t pah[4] = { phiA[2 * kt2], phiB[2 * kt2],
                                phiA[2 * kt2 + 1], phiB[2 * kt2 + 1] };
            uint32_t pal[4] = { ploA[2 * kt2], ploB[2 * kt2],
                                ploA[2 * kt2 + 1], ploB[2 * kt2 + 1] };
#pragma unroll
            for (int ntp = 0; ntp < 4; ntp++) {
                int rowB = ntp * 16 + rB0;
                uint32_t boff = rowB * 128 + (((kt2 * 2 + b_kpar) ^ (rowB & 7)) << 4);
                uint32_t vh[4], vl[4];
                LDSM_X4(vh[0], vh[1], vh[2], vh[3], sb + ASM_VHI + boff);
                LDSM_X4(vl[0], vl[1], vl[2], vl[3], sb + ASM_VLO + boff);
                MMA_BF16(o[2 * ntp], pah, vh);
                MMA_BF16(o[2 * ntp], pah, vl);
                MMA_BF16(o[2 * ntp], pal, vh);
                MMA_BF16(o[2 * ntp + 1], pah, vh + 2);
                MMA_BF16(o[2 * ntp + 1], pah, vl + 2);
                MMA_BF16(o[2 * ntp + 1], pal, vh + 2);
            }
        }
        __syncthreads();
    }

    float inv0 = 1.0f / l0, inv1 = 1.0f / l1;
    const int row0 = b * S_LEN + qb * 64 + mBase + g;
    const int row1 = row0 + 8;
#pragma unroll
    for (int t = 0; t < 8; t++) {
        int col = h * HEAD_DIM + t * 8 + 2 * tg;
        __half2 p0 = __floats2half2_rn(o[t][0] * inv0, o[t][1] * inv0);
        __half2 p1 = __floats2half2_rn(o[t][2] * inv1, o[t][3] * inv1);
        *(__half2*)(ctx + (size_t)row0 * D_MODEL + col) = p0;
        *(__half2*)(ctx + (size_t)row1 * D_MODEL + col) = p1;
    }
}

// ---------------- launcher ----------------
extern "C" void kernel_launch(void* const* d_in, const int* in_sizes, int n_in,
                              void* d_out, int out_size)
{
    const float* x   = (const float*)d_in[0];
    const float* Wq  = (const float*)d_in[1];
    const float* Wk  = (const float*)d_in[2];
    const float* Wv  = (const float*)d_in[3];
    const float* Wo  = (const float*)d_in[4];
    const float* rel = (const float*)d_in[5];

    float *qp, *kp, *vp, *bp;
    __half *xh, *whh, *whl;
    __nv_bfloat16 *qhi, *qlo, *khi, *klo, *vthi, *vtlo;
    cudaGetSymbolAddress((void**)&qp, g_q);
    cudaGetSymbolAddress((void**)&kp, g_k);
    cudaGetSymbolAddress((void**)&vp, g_v);
    cudaGetSymbolAddress((void**)&bp, g_bias);
    cudaGetSymbolAddress((void**)&xh, g_xh);
    cudaGetSymbolAddress((void**)&whh, g_whh);
    cudaGetSymbolAddress((void**)&whl, g_whl);
    cudaGetSymbolAddress((void**)&qhi, g_qhi);
    cudaGetSymbolAddress((void**)&qlo, g_qlo);
    cudaGetSymbolAddress((void**)&khi, g_khi);
    cudaGetSymbolAddress((void**)&klo, g_klo);
    cudaGetSymbolAddress((void**)&vthi, g_vthi);
    cudaGetSymbolAddress((void**)&vtlo, g_vtlo);

    const size_t WSTRIDE = (size_t)D_MODEL * D_MODEL;

    conv_x_f16<<<M_ROWS * D_MODEL / (256 * 4), 256>>>(x, xh);
    conv_wt_f16<<<dim3(32, 32, 4), dim3(32, 8)>>>(Wq, Wk, Wv, Wo, whh, whl);
    bias_kernel<<<(N_HEADS * S_LEN + 255) / 256, 256>>>(rel, bp);

    cudaFuncSetAttribute(hmma_gemm64, cudaFuncAttributeMaxDynamicSharedMemorySize,
                         G2_SMEM);
    // QKV: one fused launch, z = 0,1,2
    hmma_gemm64<<<dim3(M_ROWS / 64, D_MODEL / 64, 3), 128, G2_SMEM>>>(
        xh, whh, whl, qp, kp, vp);

    rope_conv_kernel<<<M_ROWS, 512>>>(qp, kp, qhi, qlo, khi, klo);
    vt_conv_kernel<<<dim3(S_LEN / 32, HEAD_DIM / 32, BATCH * N_HEADS),
                     dim3(32, 8)>>>(vp, vthi, vtlo);

    cudaFuncSetAttribute(attn_kernel, cudaFuncAttributeMaxDynamicSharedMemorySize,
                         ATT_SMEM);
    attn_kernel<<<dim3(S_LEN / 64, BATCH * N_HEADS), 128, ATT_SMEM>>>(
        qhi, qlo, khi, klo, vthi, vtlo, bp, xh);

    // O projection: same kernel, z = 0 selects Wo plane (offset by 3)
    hmma_gemm64<<<dim3(M_ROWS / 64, D_MODEL / 64, 1), 128, G2_SMEM>>>(
        xh, whh + 3 * WSTRIDE, whl + 3 * WSTRIDE,
        (float*)d_out, (float*)d_out, (float*)d_out);
}